// round 11
// baseline (speedup 1.0000x reference)
#include <cuda_runtime.h>
#include <cuda_fp16.h>
#include <cstdint>

#define BATCH 32
#define HH 56
#define WW 56
#define NTOK (HH*WW)            // 3136
#define CH 256
#define H2 4
#define M_ALL (BATCH*NTOK)      // 100352
#define N1 196
#define M_SR (BATCH*N1)         // 6272
#define SCALE 0.17677669529663687f

// ---------------- scratch ----------------
__device__ __half g_xh    [(size_t)M_ALL*256];
__device__ __half g_wpackT[(size_t)768*256];
__device__ float  g_bpack [768];
__device__ __half g_srwT  [(size_t)256*4096];
__device__ __half g_kv1wT [(size_t)256*256];
__device__ __half g_projwT[(size_t)256*256];
__device__ __half g_packh [(size_t)M_ALL*768];  // [lepe_lin | q1 | q2 | kv2] (half)
__device__ __half g_lepeh [(size_t)M_ALL*CH];
__device__ float  g_srp   [(size_t)4*M_SR*CH];
__device__ __half g_x1s   [(size_t)M_SR*CH];
__device__ __half g_kv1h  [(size_t)M_SR*CH];
__device__ __half g_x1h   [(size_t)M_ALL*128];
__device__ __half g_x2h   [(size_t)M_ALL*128];

// ---------------- helpers ----------------
#define CP16(dst, src) \
    asm volatile("cp.async.cg.shared.global [%0], [%1], 16;" :: "r"(dst), "l"(src))
#define MMA_F16(c, a, b) \
    asm volatile("mma.sync.aligned.m16n8k16.row.col.f32.f16.f16.f32 " \
                 "{%0,%1,%2,%3},{%4,%5,%6,%7},{%8,%9},{%0,%1,%2,%3};" \
                 : "+f"((c)[0]), "+f"((c)[1]), "+f"((c)[2]), "+f"((c)[3]) \
                 : "r"((a)[0]), "r"((a)[1]), "r"((a)[2]), "r"((a)[3]), \
                   "r"((b)[0]), "r"((b)[1]))

__device__ __forceinline__ uint32_t h2pack(float a, float b) {
    __half2 h = __floats2half2_rn(a, b);
    return *(uint32_t*)&h;
}

// fp16 GEMM tile constants
#define HSTR 40
#define HBUF (128*HSTR)                 // 5120 halves = 10240 B
#define TH_SMEM (6*HBUF*2)              // 3-stage: 61440 B
#define TP_SMEM (4*HBUF*2)              // proj, 2-stage: 40960 B

// ============ prep kernels ============
__global__ void cvt_x(const float* __restrict__ x, __half* __restrict__ xh) {
    size_t i = (size_t)blockIdx.x * 256 + threadIdx.x;
    float4 v = ((const float4*)x)[i];
    __half2* o = (__half2*)xh;
    o[2 * i]     = __floats2half2_rn(v.x, v.y);
    o[2 * i + 1] = __floats2half2_rn(v.z, v.w);
}

__global__ void pack_weightsT(const float* __restrict__ lw, const float* __restrict__ lb,
                              const float* __restrict__ q1w, const float* __restrict__ q2w,
                              const float* __restrict__ kvw,
                              __half* __restrict__ wt, float* __restrict__ bp) {
    int idx = blockIdx.x * 256 + threadIdx.x;
    if (idx < 768) bp[idx] = (idx < 256) ? lb[idx] : 0.f;
    if (idx >= 768 * 256) return;
    int c = idx >> 8, k = idx & 255;
    float v;
    if (c < 256)      v = lw[k * 256 + c];
    else if (c < 384) v = q1w[k * 128 + (c - 256)];
    else if (c < 512) v = q2w[k * 128 + (c - 384)];
    else              v = kvw[k * 256 + (c - 512)];
    wt[idx] = __float2half_rn(v);
}

__global__ void roundT(const float* __restrict__ sw, const float* __restrict__ kw,
                       const float* __restrict__ pw,
                       __half* __restrict__ st, __half* __restrict__ kt,
                       __half* __restrict__ pt) {
    int i = blockIdx.x * 256 + threadIdx.x;
    if (i < 256 * 4096) {
        int c = i >> 12, k = i & 4095;
        st[i] = __float2half_rn(sw[k * 256 + c]);
    }
    if (i < 256 * 256) {
        int c = i >> 8, k = i & 255;
        kt[i] = __float2half_rn(kw[k * 256 + c]);
        pt[i] = __float2half_rn(pw[k * 256 + c]);
    }
}

// ============ fp16 GEMM, 3-stage pipeline: C[M,N] = A[M,K] @ Bt[N,K]^T (+bias) ============
template<bool OH>
__global__ __launch_bounds__(256, 2)
void tgemm_h(const __half* __restrict__ A, const __half* __restrict__ Bt,
             const float* __restrict__ bias, void* __restrict__ Cv,
             int M, int N, int K) {
    extern __shared__ __half hs[];
    const int tid  = threadIdx.x;
    const int lane = tid & 31;
    const int warp = tid >> 5;
    const int wm = (warp >> 2) * 64;
    const int wn = (warp & 3) * 32;
    const int brow = blockIdx.y * 128;
    const int bcol = blockIdx.x * 128;
    const int lr = lane >> 2;
    const int lc = lane & 3;
    const int arow = tid >> 2;
    const int c16 = tid & 3;

    float acc[4][4][4];
    #pragma unroll
    for (int i = 0; i < 4; i++)
        #pragma unroll
        for (int j = 0; j < 4; j++)
            #pragma unroll
            for (int r = 0; r < 4; r++) acc[i][j][r] = 0.f;

    const int KT = K >> 5;
    auto issue = [&](int buf, int k0) {
        __half* Ad = hs + buf * HBUF;
        __half* Bd = hs + 3 * HBUF + buf * HBUF;
        #pragma unroll
        for (int i = 0; i < 2; i++) {
            int row = arow + i * 64;
            uint32_t d = (uint32_t)__cvta_generic_to_shared(Ad + row * HSTR + c16 * 8);
            CP16(d, A + (size_t)(brow + row) * K + k0 + c16 * 8);
        }
        #pragma unroll
        for (int i = 0; i < 2; i++) {
            int row = arow + i * 64;
            uint32_t d = (uint32_t)__cvta_generic_to_shared(Bd + row * HSTR + c16 * 8);
            CP16(d, Bt + (size_t)(bcol + row) * K + k0 + c16 * 8);
        }
        asm volatile("cp.async.commit_group;" ::);
    };

    issue(0, 0);
    if (KT > 1) issue(1, 32);
    for (int kt = 0; kt < KT; kt++) {
        asm volatile("cp.async.wait_group 1;" ::);
        __syncthreads();
        if (kt + 2 < KT) issue((kt + 2) % 3, (kt + 2) << 5);
        const int buf = kt % 3;
        const __half* Ad = hs + buf * HBUF;
        const __half* Bd = hs + 3 * HBUF + buf * HBUF;
        #pragma unroll
        for (int ks = 0; ks < 2; ks++) {
            const int kb = ks * 16 + 2 * lc;
            uint32_t af[4][4], bf[4][2];
            #pragma unroll
            for (int mi = 0; mi < 4; mi++) {
                int r0 = wm + mi * 16 + lr;
                af[mi][0] = *(const uint32_t*)(Ad + r0 * HSTR + kb);
                af[mi][1] = *(const uint32_t*)(Ad + (r0 + 8) * HSTR + kb);
                af[mi][2] = *(const uint32_t*)(Ad + r0 * HSTR + kb + 8);
                af[mi][3] = *(const uint32_t*)(Ad + (r0 + 8) * HSTR + kb + 8);
            }
            #pragma unroll
            for (int nj = 0; nj < 4; nj++) {
                int cc = wn + nj * 8 + lr;
                bf[nj][0] = *(const uint32_t*)(Bd + cc * HSTR + kb);
                bf[nj][1] = *(const uint32_t*)(Bd + cc * HSTR + kb + 8);
            }
            #pragma unroll
            for (int mi = 0; mi < 4; mi++)
                #pragma unroll
                for (int nj = 0; nj < 4; nj++)
                    MMA_F16(acc[mi][nj], af[mi], bf[nj]);
        }
    }
    #pragma unroll
    for (int mi = 0; mi < 4; mi++) {
        #pragma unroll
        for (int nj = 0; nj < 4; nj++) {
            int r0 = brow + wm + mi * 16 + lr;
            int c0 = bcol + wn + nj * 8 + lc * 2;
            float b0 = 0.f, b1 = 0.f;
            if (bias) { b0 = bias[c0]; b1 = bias[c0 + 1]; }
            if (OH) {
                __half* C = (__half*)Cv;
                *(__half2*)&C[(size_t)r0 * N + c0] =
                    __floats2half2_rn(acc[mi][nj][0] + b0, acc[mi][nj][1] + b1);
                *(__half2*)&C[(size_t)(r0 + 8) * N + c0] =
                    __floats2half2_rn(acc[mi][nj][2] + b0, acc[mi][nj][3] + b1);
            } else {
                float* C = (float*)Cv;
                *(float2*)&C[(size_t)r0 * N + c0] = make_float2(acc[mi][nj][0] + b0, acc[mi][nj][1] + b1);
                *(float2*)&C[(size_t)(r0 + 8) * N + c0] = make_float2(acc[mi][nj][2] + b0, acc[mi][nj][3] + b1);
            }
        }
    }
}

// ============ fp16 sr-conv GEMM, fused im2col, split-K x4, 3-stage ============
__global__ __launch_bounds__(256, 2)
void tgemm_sr_h(const __half* __restrict__ xh, const __half* __restrict__ Bt,
                float* __restrict__ Cp) {
    const int kc = blockIdx.z;
    float* C = Cp + (size_t)kc * M_SR * 256;
    extern __shared__ __half hs[];
    const int tid  = threadIdx.x;
    const int lane = tid & 31;
    const int warp = tid >> 5;
    const int wm = (warp >> 2) * 64;
    const int wn = (warp & 3) * 32;
    const int brow = blockIdx.y * 128;
    const int bcol = blockIdx.x * 128;
    const int lr = lane >> 2;
    const int lc = lane & 3;
    const int arow = tid >> 2;
    const int c16 = tid & 3;

    const __half* px[2];
    #pragma unroll
    for (int i = 0; i < 2; i++) {
        int m = brow + arow + i * 64;
        int b = m / 196, rem = m % 196;
        int oh = rem / 14, ow = rem % 14;
        px[i] = xh + ((size_t)((b * 56 + oh * 4) * 56 + ow * 4)) * 256;
    }

    float acc[4][4][4];
    #pragma unroll
    for (int i = 0; i < 4; i++)
        #pragma unroll
        for (int j = 0; j < 4; j++)
            #pragma unroll
            for (int r = 0; r < 4; r++) acc[i][j][r] = 0.f;

    const int KT = 32;
    auto issue = [&](int buf, int k0) {
        __half* Ad = hs + buf * HBUF;
        __half* Bd = hs + 3 * HBUF + buf * HBUF;
        int kk = kc * 1024 + k0 + c16 * 8;
        int kh = kk >> 10, kw = (kk >> 8) & 3, c = kk & 255;
        int off = (kh * 56 + kw) * 256 + c;
        #pragma unroll
        for (int i = 0; i < 2; i++) {
            int row = arow + i * 64;
            uint32_t d = (uint32_t)__cvta_generic_to_shared(Ad + row * HSTR + c16 * 8);
            CP16(d, px[i] + off);
        }
        #pragma unroll
        for (int i = 0; i < 2; i++) {
            int row = arow + i * 64;
            uint32_t d = (uint32_t)__cvta_generic_to_shared(Bd + row * HSTR + c16 * 8);
            CP16(d, Bt + (size_t)(bcol + row) * 4096 + kc * 1024 + k0 + c16 * 8);
        }
        asm volatile("cp.async.commit_group;" ::);
    };

    issue(0, 0);
    issue(1, 32);
    for (int kt = 0; kt < KT; kt++) {
        asm volatile("cp.async.wait_group 1;" ::);
        __syncthreads();
        if (kt + 2 < KT) issue((kt + 2) % 3, (kt + 2) << 5);
        const int buf = kt % 3;
        const __half* Ad = hs + buf * HBUF;
        const __half* Bd = hs + 3 * HBUF + buf * HBUF;
        #pragma unroll
        for (int ks = 0; ks < 2; ks++) {
            const int kb = ks * 16 + 2 * lc;
            uint32_t af[4][4], bf[4][2];
            #pragma unroll
            for (int mi = 0; mi < 4; mi++) {
                int r0 = wm + mi * 16 + lr;
                af[mi][0] = *(const uint32_t*)(Ad + r0 * HSTR + kb);
                af[mi][1] = *(const uint32_t*)(Ad + (r0 + 8) * HSTR + kb);
                af[mi][2] = *(const uint32_t*)(Ad + r0 * HSTR + kb + 8);
                af[mi][3] = *(const uint32_t*)(Ad + (r0 + 8) * HSTR + kb + 8);
            }
            #pragma unroll
            for (int nj = 0; nj < 4; nj++) {
                int cc = wn + nj * 8 + lr;
                bf[nj][0] = *(const uint32_t*)(Bd + cc * HSTR + kb);
                bf[nj][1] = *(const uint32_t*)(Bd + cc * HSTR + kb + 8);
            }
            #pragma unroll
            for (int mi = 0; mi < 4; mi++)
                #pragma unroll
                for (int nj = 0; nj < 4; nj++)
                    MMA_F16(acc[mi][nj], af[mi], bf[nj]);
        }
    }
    #pragma unroll
    for (int mi = 0; mi < 4; mi++) {
        #pragma unroll
        for (int nj = 0; nj < 4; nj++) {
            int r0 = brow + wm + mi * 16 + lr;
            int c0 = bcol + wn + nj * 8 + lc * 2;
            *(float2*)&C[(size_t)r0 * 256 + c0] = make_float2(acc[mi][nj][0], acc[mi][nj][1]);
            *(float2*)&C[(size_t)(r0 + 8) * 256 + c0] = make_float2(acc[mi][nj][2], acc[mi][nj][3]);
        }
    }
}

// ============ fp16 proj GEMM with fused concat(x1,x2)+lepe (2-stage) ============
__global__ __launch_bounds__(256, 2)
void tgemm_proj_h(const __half* __restrict__ x1h, const __half* __restrict__ x2h,
                  const __half* __restrict__ lepeh, const __half* __restrict__ Bt,
                  const float* __restrict__ bias, float* __restrict__ C) {
    const int N = 256, K = 256;
    extern __shared__ __half hs[];
    const int tid  = threadIdx.x;
    const int lane = tid & 31;
    const int warp = tid >> 5;
    const int wm = (warp >> 2) * 64;
    const int wn = (warp & 3) * 32;
    const int brow = blockIdx.y * 128;
    const int bcol = blockIdx.x * 128;
    const int lr = lane >> 2;
    const int lc = lane & 3;
    const int arow = tid >> 2;
    const int c16 = tid & 3;

    float acc[4][4][4];
    #pragma unroll
    for (int i = 0; i < 4; i++)
        #pragma unroll
        for (int j = 0; j < 4; j++)
            #pragma unroll
            for (int r = 0; r < 4; r++) acc[i][j][r] = 0.f;

    auto issueB = [&](int buf, int k0) {
        __half* Bd = hs + 2 * HBUF + buf * HBUF;
        #pragma unroll
        for (int i = 0; i < 2; i++) {
            int row = arow + i * 64;
            uint32_t d = (uint32_t)__cvta_generic_to_shared(Bd + row * HSTR + c16 * 8);
            CP16(d, Bt + (size_t)(bcol + row) * K + k0 + c16 * 8);
        }
        asm volatile("cp.async.commit_group;" ::);
    };

    uint4 ra4[2];
    auto addh = [](uint32_t ua, uint32_t ul) {
        __half2 ha = *(__half2*)&ua, hl = *(__half2*)&ul;
        float2 fa = __half22float2(ha), fl = __half22float2(hl);
        __half2 r = __floats2half2_rn(fa.x + fl.x, fa.y + fl.y);
        return *(uint32_t*)&r;
    };
    auto loadA = [&](int k0) {
        int kk = k0 + c16 * 8;
        #pragma unroll
        for (int i = 0; i < 2; i++) {
            size_t m = (size_t)(brow + arow + i * 64);
            uint4 a = (kk < 128) ? *(const uint4*)&x1h[m * 128 + kk]
                                 : *(const uint4*)&x2h[m * 128 + kk - 128];
            uint4 l = *(const uint4*)&lepeh[m * 256 + kk];
            ra4[i].x = addh(a.x, l.x);
            ra4[i].y = addh(a.y, l.y);
            ra4[i].z = addh(a.z, l.z);
            ra4[i].w = addh(a.w, l.w);
        }
    };
    auto storeA = [&](int buf) {
        __half* Ad = hs + buf * HBUF;
        #pragma unroll
        for (int i = 0; i < 2; i++)
            *(uint4*)(Ad + (arow + i * 64) * HSTR + c16 * 8) = ra4[i];
    };

    issueB(0, 0);
    loadA(0);
    int buf = 0;
    const int KT = K >> 5;
    for (int kt = 0; kt < KT; kt++) {
        storeA(buf);
        asm volatile("cp.async.wait_group 0;" ::);
        __syncthreads();
        if (kt + 1 < KT) { issueB(buf ^ 1, (kt + 1) << 5); loadA((kt + 1) << 5); }
        const __half* Ad = hs + buf * HBUF;
        const __half* Bd = hs + 2 * HBUF + buf * HBUF;
        #pragma unroll
        for (int ks = 0; ks < 2; ks++) {
            const int kb = ks * 16 + 2 * lc;
            uint32_t af[4][4], bf[4][2];
            #pragma unroll
            for (int mi = 0; mi < 4; mi++) {
                int r0 = wm + mi * 16 + lr;
                af[mi][0] = *(const uint32_t*)(Ad + r0 * HSTR + kb);
                af[mi][1] = *(const uint32_t*)(Ad + (r0 + 8) * HSTR + kb);
                af[mi][2] = *(const uint32_t*)(Ad + r0 * HSTR + kb + 8);
                af[mi][3] = *(const uint32_t*)(Ad + (r0 + 8) * HSTR + kb + 8);
            }
            #pragma unroll
            for (int nj = 0; nj < 4; nj++) {
                int cc = wn + nj * 8 + lr;
                bf[nj][0] = *(const uint32_t*)(Bd + cc * HSTR + kb);
                bf[nj][1] = *(const uint32_t*)(Bd + cc * HSTR + kb + 8);
            }
            #pragma unroll
            for (int mi = 0; mi < 4; mi++)
                #pragma unroll
                for (int nj = 0; nj < 4; nj++)
                    MMA_F16(acc[mi][nj], af[mi], bf[nj]);
        }
        buf ^= 1;
        __syncthreads();
    }
    #pragma unroll
    for (int mi = 0; mi < 4; mi++) {
        #pragma unroll
        for (int nj = 0; nj < 4; nj++) {
            int r0 = brow + wm + mi * 16 + lr;
            int c0 = bcol + wn + nj * 8 + lc * 2;
            float b0 = bias[c0], b1 = bias[c0 + 1];
            *(float2*)&C[(size_t)r0 * N + c0] = make_float2(acc[mi][nj][0] + b0, acc[mi][nj][1] + b1);
            *(float2*)&C[(size_t)(r0 + 8) * N + c0] = make_float2(acc[mi][nj][2] + b0, acc[mi][nj][3] + b1);
        }
    }
}

// ============ depthwise 3x3, half2 vectorized (2 channels/thread) ============
__global__ void dwconv3x3(const __half* __restrict__ in, const float* __restrict__ w,
                          const float* __restrict__ bias, __half* __restrict__ out) {
    int idx = blockIdx.x * 256 + threadIdx.x;   // (b, xx, c2)
    int c2 = idx & 127;
    int t = idx >> 7;
    int xx = t % WW, b = t / WW;
    int c = c2 * 2;
    float2 wt[9];
    #pragma unroll
    for (int i = 0; i < 9; i++) wt[i] = *(const float2*)&w[i * 256 + c];
    float2 bz = *(const float2*)&bias[c];
    const __half2* base = (const __half2*)in + (size_t)b * NTOK * 384 + c2;  // stride 384 h2/token
    __half2* ob = (__half2*)out + (size_t)b * NTOK * 128 + c2;
    bool xl = xx > 0, xr = xx < WW - 1;

    float2 rA[3], rB[3], rC[3];
    #pragma unroll
    for (int i = 0; i < 3; i++) rA[i] = make_float2(0.f, 0.f);
    {
        rB[0] = xl ? __half22float2(base[(size_t)(xx - 1) * 384]) : make_float2(0.f, 0.f);
        rB[1] = __half22float2(base[(size_t)xx * 384]);
        rB[2] = xr ? __half22float2(base[(size_t)(xx + 1) * 384]) : make_float2(0.f, 0.f);
    }
    for (int y = 0; y < HH; y++) {
        if (y + 1 < HH) {
            const __half2* rp = base + (size_t)(y + 1) * WW * 384;
            rC[0] = xl ? __half22float2(rp[(size_t)(xx - 1) * 384]) : make_float2(0.f, 0.f);
            rC[1] = __half22float2(rp[(size_t)xx * 384]);
            rC[2] = xr ? __half22float2(rp[(size_t)(xx + 1) * 384]) : make_float2(0.f, 0.f);
        } else { rC[0] = rC[1] = rC[2] = make_float2(0.f, 0.f); }
        float ax = bz.x, ay = bz.y;
        #pragma unroll
        for (int i = 0; i < 3; i++) {
            ax += wt[i].x * rA[i].x + wt[3 + i].x * rB[i].x + wt[6 + i].x * rC[i].x;
            ay += wt[i].y * rA[i].y + wt[3 + i].y * rB[i].y + wt[6 + i].y * rC[i].y;
        }
        ob[(size_t)(y * WW + xx) * 128] = __floats2half2_rn(ax, ay);
        #pragma unroll
        for (int i = 0; i < 3; i++) { rA[i] = rB[i]; rB[i] = rC[i]; }
    }
}

// ============ split-K reduce + bias + LayerNorm + GELU -> half ============
__global__ void ln_gelu4(const float* __restrict__ p, const float* __restrict__ srb,
                         const float* __restrict__ g, const float* __restrict__ bb,
                         __half* __restrict__ xb) {
    int row = blockIdx.x;
    int tid = threadIdx.x;
    const size_t S = (size_t)M_SR * 256;
    size_t off = (size_t)row * 256 + tid;
    float v = p[off] + p[S + off] + p[2 * S + off] + p[3 * S + off] + srb[tid];
    __shared__ float s1[256], s2[256];
    s1[tid] = v; s2[tid] = v * v;
    __syncthreads();
    for (int o = 128; o; o >>= 1) {
        if (tid < o) { s1[tid] += s1[tid + o]; s2[tid] += s2[tid + o]; }
        __syncthreads();
    }
    float mu  = s1[0] * (1.f / CH);
    float var = s2[0] * (1.f / CH) - mu * mu;
    float tt = (v - mu) * rsqrtf(var + 1e-5f) * g[tid] + bb[tid];
    xb[off] = __float2half_rn(0.5f * tt * (1.f + erff(tt * 0.70710678118654752f)));
}

// ============ branch-1 attention, fp16 MMA ============
#define A1_SMEM 96256
__global__ __launch_bounds__(256, 2)
void attn1_mma(const __half* __restrict__ packh, const __half* __restrict__ kv1h,
               __half* __restrict__ x1h) {
    extern __shared__ __half smh[];
    __half* Qs = smh;                        // [64][40]
    __half* Ks = smh + 2560;                 // [224][40] rows 196..223 zero
    __half* Vt = smh + 2560 + 8960;          // [32][232] cols 196..223 zero
    float*  Ss = (float*)(smh + 18944);      // [64][228]
    int bh = blockIdx.y, b = bh >> 2, h = bh & 3;
    int q0 = blockIdx.x * 64;
    int tid = threadIdx.x, lane = tid & 31, warp = tid >> 5;
    int lr = lane >> 2, lc = lane & 3;

    {
        int r = tid >> 2, ch = tid & 3;
        *(uint4*)&Qs[r * 40 + ch * 8] =
            *(const uint4*)&packh[((size_t)b * NTOK + q0 + r) * 768 + 256 + h * 32 + ch * 8];
    }
    for (int e = tid; e < 224 * 4; e += 256) {
        int r = e >> 2, ch = e & 3;
        uint4 v = make_uint4(0u, 0u, 0u, 0u);
        if (r < 196)
            v = *(const uint4*)&kv1h[((size_t)b * N1 + r) * 256 + h * 32 + ch * 8];
        *(uint4*)&Ks[r * 40 + ch * 8] = v;
    }
    for (int e = tid; e < 224 * 32; e += 256) {
        int m = e >> 5, dd = e & 31;
        __half v = __float2half_rn(0.f);
        if (m < 196) v = kv1h[((size_t)b * N1 + m) * 256 + 128 + h * 32 + dd];
        Vt[dd * 232 + m] = v;
    }
    __syncthreads();

    {
        int wm = (warp >> 2) * 32, wn = (warp & 3) * 56;
        float acc[2][7][4];
        #pragma unroll
        for (int i = 0; i < 2; i++)
            #pragma unroll
            for (int j = 0; j < 7; j++)
                #pragma unroll
                for (int r = 0; r < 4; r++) acc[i][j][r] = 0.f;
        #pragma unroll
        for (int ks = 0; ks < 2; ks++) {
            const int kb = ks * 16 + 2 * lc;
            uint32_t af[2][4], bf[7][2];
            #pragma unroll
            for (int mi = 0; mi < 2; mi++) {
                int r0 = wm + mi * 16 + lr;
                af[mi][0] = *(const uint32_t*)(Qs + r0 * 40 + kb);
                af[mi][1] = *(const uint32_t*)(Qs + (r0 + 8) * 40 + kb);
                af[mi][2] = *(const uint32_t*)(Qs + r0 * 40 + kb + 8);
                af[mi][3] = *(const uint32_t*)(Qs + (r0 + 8) * 40 + kb + 8);
            }
            #pragma unroll
            for (int nj = 0; nj < 7; nj++) {
                int cc = wn + nj * 8 + lr;
                bf[nj][0] = *(const uint32_t*)(Ks + cc * 40 + kb);
                bf[nj][1] = *(const uint32_t*)(Ks + cc * 40 + kb + 8);
            }
            #pragma unroll
            for (int mi = 0; mi < 2; mi++)
                #pragma unroll
                for (int nj = 0; nj < 7; nj++)
                    MMA_F16(acc[mi][nj], af[mi], bf[nj]);
        }
        #pragma unroll
        for (int mi = 0; mi < 2; mi++)
            #pragma unroll
            for (int nj = 0; nj < 7; nj++) {
                int r0 = wm + mi * 16 + lr;
                int c0 = wn + nj * 8 + lc * 2;
                Ss[r0 * 228 + c0]           = acc[mi][nj][0] * SCALE;
                Ss[r0 * 228 + c0 + 1]       = acc[mi][nj][1] * SCALE;
                Ss[(r0 + 8) * 228 + c0]     = acc[mi][nj][2] * SCALE;
                Ss[(r0 + 8) * 228 + c0 + 1] = acc[mi][nj][3] * SCALE;
            }
    }
    __syncthreads();

    #pragma unroll
    for (int r = 0; r < 8; r++) {
        int row = warp * 8 + r;
        float mx = -1e30f;
        for (int m = lane; m < 196; m += 32) mx = fmaxf(mx, Ss[row * 228 + m]);
        #pragma unroll
        for (int o = 16; o; o >>= 1) mx = fmaxf(mx, __shfl_xor_sync(0xffffffffu, mx, o));
        float sum = 0.f;
        for (int m = lane; m < 196; m += 32) {
            float p = __expf(Ss[row * 228 + m] - mx);
            Ss[row * 228 + m] = p;
            sum += p;
        }
        #pragma unroll
        for (int o = 16; o; o >>= 1) sum += __shfl_xor_sync(0xffffffffu, sum, o);
        float inv = 1.f / sum;
        for (int m = lane; m < 196; m += 32) Ss[row * 228 + m] *= inv;
    }
    __syncthreads();

    {
        int wm = (warp >> 1) * 16, wn = (warp & 1) * 16;
        float acc[2][4];
        #pragma unroll
        for (int j = 0; j < 2; j++)
            #pragma unroll
            for (int r = 0; r < 4; r++) acc[j][r] = 0.f;
        #pragma unroll 7
        for (int ks = 0; ks < 14; ks++) {
            const int k = ks * 16;
            const float* S0 = Ss + (wm + lr) * 228 + k + 2 * lc;
            const float* S1 = Ss + (wm + 8 + lr) * 228 + k + 2 * lc;
            uint32_t af[4], bf[2][2];
            float2 p0 = *(const float2*)S0;
            float2 p1 = *(const float2*)S1;
            float2 p2 = *(const float2*)(S0 + 8);
            float2 p3 = *(const float2*)(S1 + 8);
            af[0] = h2pack(p0.x, p0.y);
            af[1] = h2pack(p1.x, p1.y);
            af[2] = h2pack(p2.x, p2.y);
            af[3] = h2pack(p3.x, p3.y);
            #pragma unroll
            for (int nj = 0; nj < 2; nj++) {
                int cc = wn + nj * 8 + lr;
                bf[nj][0] = *(const uint32_t*)(Vt + cc * 232 + k + 2 * lc);
                bf[nj][1] = *(const uint32_t*)(Vt + cc * 232 + k + 2 * lc + 8);
            }
            MMA_F16(acc[0], af, bf[0]);
            MMA_F16(acc[1], af, bf[1]);
        }
        #pragma unroll
        for (int nj = 0; nj < 2; nj++) {
            int r0 = q0 + wm + lr;
            int c0 = wn + nj * 8 + lc * 2;
            *(__half2*)&x1h[((size_t)b * NTOK + r0) * 128 + h * 32 + c0] =
                __floats2half2_rn(acc[nj][0], acc[nj][1]);
            *(__half2*)&x1h[((size_t)b * NTOK + r0 + 8) * 128 + h * 32 + c0] =
                __floats2half2_rn(acc[nj][2], acc[nj][3]);
        }
    }
}

// ============ branch-2 window attention, fp16 MMA, 2 windows/CTA ============
#define A2_WBYTES 32256
#define A2_SMEM (2 * A2_WBYTES)
__global__ __launch_bounds__(256, 3)
void attn2_mma(const __half* __restrict__ packh, __half* __restrict__ x2h) {
    extern __shared__ char smc[];
    int bh = blockIdx.y, b = bh >> 2, h = bh & 3;
    int tid = threadIdx.x, lane = tid & 31, warp = tid >> 5;
    int wslot = warp >> 2, w4 = warp & 3;
    int lr = lane >> 2, lc = lane & 3;
    int win = blockIdx.x * 2 + wslot;
    int wr = win >> 3, wc = win & 7;
    char* wbase = smc + wslot * A2_WBYTES;
    __half* Qs = (__half*)wbase;             // [64][40], rows 49..63 zero
    __half* Ks = Qs + 2560;                  // [64][40], rows 49..63 zero
    __half* Vt = Ks + 2560;                  // [32][72], cols 49..63 zero
    float*  Ss = (float*)(wbase + 14848);    // [64][68]
    int wt = tid & 127;

    for (int e = wt; e < 64 * 4; e += 128) {
        int r = e >> 2, ch = e & 3;
        uint4 q = make_uint4(0u, 0u, 0u, 0u), k = q;
        if (r < 49) {
            int n = (wr * 7 + r / 7) * 56 + wc * 7 + r % 7;
            size_t rb = ((size_t)b * NTOK + n) * 768;
            q = *(const uint4*)&packh[rb + 384 + h * 32 + ch * 8];
            k = *(const uint4*)&packh[rb + 512 + h * 32 + ch * 8];
        }
        *(uint4*)&Qs[r * 40 + ch * 8] = q;
        *(uint4*)&Ks[r * 40 + ch * 8] = k;
    }
    for (int e = wt; e < 64 * 32; e += 128) {
        int m = e >> 5, dd = e & 31;
        __half v = __float2half_rn(0.f);
        if (m < 49) {
            int n = (wr * 7 + m / 7) * 56 + wc * 7 + m % 7;
            v = packh[((size_t)b * NTOK + n) * 768 + 640 + h * 32 + dd];
        }
        Vt[dd * 72 + m] = v;
    }
    __syncthreads();

    int wm = w4 * 16;
    {
        float acc[8][4];
        #pragma unroll
        for (int j = 0; j < 8; j++)
            #pragma unroll
            for (int r = 0; r < 4; r++) acc[j][r] = 0.f;
        #pragma unroll
        for (int ks = 0; ks < 2; ks++) {
            const int kb = ks * 16 + 2 * lc;
            uint32_t af[4], bf[8][2];
            af[0] = *(const uint32_t*)(Qs + (wm + lr) * 40 + kb);
            af[1] = *(const uint32_t*)(Qs + (wm + 8 + lr) * 40 + kb);
            af[2] = *(const uint32_t*)(Qs + (wm + lr) * 40 + kb + 8);
            af[3] = *(const uint32_t*)(Qs + (wm + 8 + lr) * 40 + kb + 8);
            #pragma unroll
            for (int nj = 0; nj < 8; nj++) {
                int cc = nj * 8 + lr;
                bf[nj][0] = *(const uint32_t*)(Ks + cc * 40 + kb);
                bf[nj][1] = *(const uint32_t*)(Ks + cc * 40 + kb + 8);
            }
            #pragma unroll
            for (int nj = 0; nj < 8; nj++)
                MMA_F16(acc[nj], af, bf[nj]);
        }
        #pragma unroll
        for (int nj = 0; nj < 8; nj++) {
            int c0 = nj * 8 + lc * 2;
            Ss[(wm + lr) * 68 + c0]           = acc[nj][0] * SCALE;
            Ss[(wm + lr) * 68 + c0 + 1]       = acc[nj][1] * SCALE;
            Ss[(wm + 8 + lr) * 68 + c0]       = acc[nj][2] * SCALE;
            Ss[(wm + 8 + lr) * 68 + c0 + 1]   = acc[nj][3] * SCALE;
        }
    }
    __syncthreads();

    for (int row = w4; row < 49; row += 4) {
        float mx = -1e30f;
        for (int m = lane; m < 49; m += 32) mx = fmaxf(mx, Ss[row * 68 + m]);
        #pragma unroll
        for (int o = 16; o; o >>= 1) mx = fmaxf(mx, __shfl_xor_sync(0xffffffffu, mx, o));
        float sum = 0.f;
        for (int m = lane; m < 49; m += 32) {
            float p = __expf(Ss[row * 68 + m] - mx);
            Ss[row * 68 + m] = p;
            sum += p;
        }
        #pragma unroll
        for (int o = 16; o; o >>= 1) sum += __shfl_xor_sync(0xffffffffu, sum, o);
        float inv = 1.f / sum;
        for (int m = lane; m < 49; m += 32) Ss[row * 68 + m] *= inv;
    }
    __syncthreads();

    {
        float acc[4][4];
        #pragma unroll
        for (int j = 0; j < 4; j++)
            #pragma unroll
            for (int r = 0; r < 4; r++) acc[j][r] = 0.f;
        #pragma unroll
        for (int ks = 0; ks < 4; ks++) {
            const int k = ks * 16;
            const float* S0 = Ss + (wm + lr) * 68 + k + 2 * lc;
            const float* S1 = Ss + (wm + 8 + lr) * 68 + k + 2 * lc;
            uint32_t af[4], bf[4][2];
            float2 p0 = *(const float2*)S0;
            float2 p1 = *(const float2*)S1;
            float2 p2 = *(const float2*)(S0 + 8);
            float2 p3 = *(const float2*)(S1 + 8);
            af[0] = h2pack(p0.x, p0.y);
            af[1] = h2pack(p1.x, p1.y);
            af[2] = h2pack(p2.x, p2.y);
            af[3] = h2pack(p3.x, p3.y);
            #pragma unroll
            for (int nj = 0; nj < 4; nj++) {
                int cc = nj * 8 + lr;
                bf[nj][0] = *(const uint32_t*)(Vt + cc * 72 + k + 2 * lc);
                bf[nj][1] = *(const uint32_t*)(Vt + cc * 72 + k + 2 * lc + 8);
            }
            #pragma unroll
            for (int nj = 0; nj < 4; nj++)
                MMA_F16(acc[nj], af, bf[nj]);
        }
        int r1 = wm + lr, r2 = wm + 8 + lr;
        #pragma unroll
        for (int nj = 0; nj < 4; nj++) {
            int c0 = nj * 8 + lc * 2;
            if (r1 < 49) {
                int n = (wr * 7 + r1 / 7) * 56 + wc * 7 + r1 % 7;
                *(__half2*)&x2h[((size_t)b * NTOK + n) * 128 + h * 32 + c0] =
                    __floats2half2_rn(acc[nj][0], acc[nj][1]);
            }
            if (r2 < 49) {
                int n = (wr * 7 + r2 / 7) * 56 + wc * 7 + r2 % 7;
                *(__half2*)&x2h[((size_t)b * NTOK + n) * 128 + h * 32 + c0] =
                    __floats2half2_rn(acc[nj][2], acc[nj][3]);
            }
        }
    }
}

// ---------------- host launch ----------------
extern "C" void kernel_launch(void* const* d_in, const int* in_sizes, int n_in,
                              void* d_out, int out_size) {
    const float* x           = (const float*)d_in[0];
    const float* lepe_lin_w  = (const float*)d_in[1];
    const float* lepe_lin_b  = (const float*)d_in[2];
    const float* lepe_conv_w = (const float*)d_in[3];
    const float* lepe_conv_b = (const float*)d_in[4];
    const float* sr_w        = (const float*)d_in[5];
    const float* sr_b        = (const float*)d_in[6];
    const float* norm_g      = (const float*)d_in[7];
    const float* norm_b      = (const float*)d_in[8];
    const float* q1_w        = (const float*)d_in[9];
    const float* kv1_w       = (const float*)d_in[10];
    const float* q2_w        = (const float*)d_in[11];
    const float* kv2_w       = (const float*)d_in[12];
    const float* proj_w      = (const float*)d_in[13];
    const float* proj_b      = (const float*)d_in[14];
    float* out = (float*)d_out;

    __half *xh, *wpackT, *srwT, *kv1wT, *projwT, *packh, *lepeh, *x1s, *kv1h, *x1h, *x2h;
    float *bpack, *srp;
    cudaGetSymbolAddress((void**)&xh,     g_xh);
    cudaGetSymbolAddress((void**)&wpackT, g_wpackT);
    cudaGetSymbolAddress((void**)&bpack,  g_bpack);
    cudaGetSymbolAddress((void**)&srwT,   g_srwT);
    cudaGetSymbolAddress((void**)&kv1wT,  g_kv1wT);
    cudaGetSymbolAddress((void**)&projwT, g_projwT);
    cudaGetSymbolAddress((void**)&packh,  g_packh);
    cudaGetSymbolAddress((void**)&lepeh,  g_lepeh);
    cudaGetSymbolAddress((void**)&srp,    g_srp);
    cudaGetSymbolAddress((void**)&x1s,    g_x1s);
    cudaGetSymbolAddress((void**)&kv1h,   g_kv1h);
    cudaGetSymbolAddress((void**)&x1h,    g_x1h);
    cudaGetSymbolAddress((void**)&x2h,    g_x2h);

    cudaFuncSetAttribute(tgemm_h<true>,  cudaFuncAttributeMaxDynamicSharedMemorySize, TH_SMEM);
    cudaFuncSetAttribute(tgemm_h<false>, cudaFuncAttributeMaxDynamicSharedMemorySize, TH_SMEM);
    cudaFuncSetAttribute(tgemm_sr_h,     cudaFuncAttributeMaxDynamicSharedMemorySize, TH_SMEM);
    cudaFuncSetAttribute(tgemm_proj_h,   cudaFuncAttributeMaxDynamicSharedMemorySize, TP_SMEM);
    cudaFuncSetAttribute(attn1_mma,      cudaFuncAttributeMaxDynamicSharedMemorySize, A1_SMEM);
    cudaFuncSetAttribute(attn2_mma,      cudaFuncAttributeMaxDynamicSharedMemorySize, A2_SMEM);

    static cudaStream_t s1 = nullptr, s2 = nullptr;
    static cudaEvent_t evF = nullptr, evP = nullptr, evJ1 = nullptr, evJ2 = nullptr;
    if (!s1) {
        cudaStreamCreateWithFlags(&s1, cudaStreamNonBlocking);
        cudaStreamCreateWithFlags(&s2, cudaStreamNonBlocking);
        cudaEventCreateWithFlags(&evF, cudaEventDisableTiming);
        cudaEventCreateWithFlags(&evP, cudaEventDisableTiming);
        cudaEventCreateWithFlags(&evJ1, cudaEventDisableTiming);
        cudaEventCreateWithFlags(&evJ2, cudaEventDisableTiming);
    }

    // main: weight pack + x conversion
    pack_weightsT<<<768, 256>>>(lepe_lin_w, lepe_lin_b, q1_w, q2_w, kv2_w, wpackT, bpack);
    cvt_x<<<(M_ALL * 256 / 4) / 256, 256>>>(x, xh);
    cudaEventRecord(evF, 0);

    // s1: sr chain
    roundT<<<4096, 256, 0, s1>>>(sr_w, kv1_w, proj_w, srwT, kv1wT, projwT);
    cudaStreamWaitEvent(s1, evF, 0);
    tgemm_sr_h<<<dim3(2, M_SR / 128, 4), 256, TH_SMEM, s1>>>(xh, srwT, srp);
    ln_gelu4<<<M_SR, 256, 0, s1>>>(srp, sr_b, norm_g, norm_b, x1s);
    tgemm_h<true><<<dim3(2, M_SR / 128), 256, TH_SMEM, s1>>>(x1s, kv1wT, nullptr, kv1h, M_SR, 256, 256);

    // main: merged projection GEMM (half out)
    tgemm_h<true><<<dim3(6, M_ALL / 128), 256, TH_SMEM>>>(xh, wpackT, bpack, packh, M_ALL, 768, 256);
    cudaEventRecord(evP, 0);
    // main: dwconv  ∥  s2: attn2  ∥  s1: attn1
    dwconv3x3<<<(BATCH * WW * 128) / 256, 256>>>(packh, lepe_conv_w, lepe_conv_b, lepeh);
    cudaStreamWaitEvent(s2, evP, 0);
    attn2_mma<<<dim3(32, BATCH * H2), 256, A2_SMEM, s2>>>(packh, x2h);
    cudaEventRecord(evJ2, s2);
    cudaStreamWaitEvent(s1, evP, 0);
    attn1_mma<<<dim3(NTOK / 64, BATCH * H2), 256, A1_SMEM, s1>>>(packh, kv1h, x1h);
    cudaEventRecord(evJ1, s1);

    // join + final projection (fp32 out)
    cudaStreamWaitEvent(0, evJ1, 0);
    cudaStreamWaitEvent(0, evJ2, 0);
    tgemm_proj_h<<<dim3(2, M_ALL / 128), 256, TP_SMEM>>>(x1h, x2h, lepeh, projwT, proj_b, out);
}

// round 14
// speedup vs baseline: 1.1671x; 1.1671x over previous
#include <cuda_runtime.h>
#include <cuda_fp16.h>
#include <cstdint>

#define BATCH 32
#define HH 56
#define WW 56
#define NTOK (HH*WW)            // 3136
#define CH 256
#define H2 4
#define M_ALL (BATCH*NTOK)      // 100352
#define N1 196
#define M_SR (BATCH*N1)         // 6272
#define SCALE 0.17677669529663687f

// ---------------- scratch ----------------
__device__ __half g_xh    [(size_t)M_ALL*256];
__device__ __half g_wpackT[(size_t)768*256];
__device__ float  g_bpack [768];
__device__ __half g_srwT  [(size_t)256*4096];
__device__ __half g_kv1wT [(size_t)256*256];
__device__ __half g_projwT[(size_t)256*256];
__device__ __half g_packh [(size_t)M_ALL*768];  // [lepe_lin | q1 | q2 | kv2] (half)
__device__ __half g_lepeh [(size_t)M_ALL*CH];
__device__ float  g_srp   [(size_t)4*M_SR*CH];
__device__ __half g_x1s   [(size_t)M_SR*CH];
__device__ __half g_kv1h  [(size_t)M_SR*CH];
__device__ __half g_x1h   [(size_t)M_ALL*128];
__device__ __half g_x2h   [(size_t)M_ALL*128];

// ---------------- helpers ----------------
#define CP16(dst, src) \
    asm volatile("cp.async.cg.shared.global [%0], [%1], 16;" :: "r"(dst), "l"(src))
#define MMA_F16(c, a, b) \
    asm volatile("mma.sync.aligned.m16n8k16.row.col.f32.f16.f16.f32 " \
                 "{%0,%1,%2,%3},{%4,%5,%6,%7},{%8,%9},{%0,%1,%2,%3};" \
                 : "+f"((c)[0]), "+f"((c)[1]), "+f"((c)[2]), "+f"((c)[3]) \
                 : "r"((a)[0]), "r"((a)[1]), "r"((a)[2]), "r"((a)[3]), \
                   "r"((b)[0]), "r"((b)[1]))

// fp16 GEMM tile constants
#define HSTR 40
#define HBUF (128*HSTR)                 // 5120 halves = 10240 B
#define TH_SMEM (6*HBUF*2)              // 3-stage: 61440 B
#define TP_SMEM (4*HBUF*2)              // proj, 2-stage: 40960 B

// ============ prep kernels ============
__global__ void cvt_x(const float* __restrict__ x, __half* __restrict__ xh) {
    size_t i = (size_t)blockIdx.x * 256 + threadIdx.x;
    float4 v = ((const float4*)x)[i];
    __half2* o = (__half2*)xh;
    o[2 * i]     = __floats2half2_rn(v.x, v.y);
    o[2 * i + 1] = __floats2half2_rn(v.z, v.w);
}

__global__ void pack_weightsT(const float* __restrict__ lw, const float* __restrict__ lb,
                              const float* __restrict__ q1w, const float* __restrict__ q2w,
                              const float* __restrict__ kvw,
                              __half* __restrict__ wt, float* __restrict__ bp) {
    int idx = blockIdx.x * 256 + threadIdx.x;
    if (idx < 768) bp[idx] = (idx < 256) ? lb[idx] : 0.f;
    if (idx >= 768 * 256) return;
    int c = idx >> 8, k = idx & 255;
    float v;
    if (c < 256)      v = lw[k * 256 + c];
    else if (c < 384) v = q1w[k * 128 + (c - 256)];
    else if (c < 512) v = q2w[k * 128 + (c - 384)];
    else              v = kvw[k * 256 + (c - 512)];
    wt[idx] = __float2half_rn(v);
}

__global__ void roundT(const float* __restrict__ sw, const float* __restrict__ kw,
                       const float* __restrict__ pw,
                       __half* __restrict__ st, __half* __restrict__ kt,
                       __half* __restrict__ pt) {
    int i = blockIdx.x * 256 + threadIdx.x;
    if (i < 256 * 4096) {
        int c = i >> 12, k = i & 4095;
        st[i] = __float2half_rn(sw[k * 256 + c]);
    }
    if (i < 256 * 256) {
        int c = i >> 8, k = i & 255;
        kt[i] = __float2half_rn(kw[k * 256 + c]);
        pt[i] = __float2half_rn(pw[k * 256 + c]);
    }
}

// ============ fp16 GEMM, 3-stage pipeline: C[M,N] = A[M,K] @ Bt[N,K]^T (+bias) ============
template<bool OH>
__global__ __launch_bounds__(256, 2)
void tgemm_h(const __half* __restrict__ A, const __half* __restrict__ Bt,
             const float* __restrict__ bias, void* __restrict__ Cv,
             int M, int N, int K) {
    extern __shared__ __half hs[];
    const int tid  = threadIdx.x;
    const int lane = tid & 31;
    const int warp = tid >> 5;
    const int wm = (warp >> 2) * 64;
    const int wn = (warp & 3) * 32;
    const int brow = blockIdx.y * 128;
    const int bcol = blockIdx.x * 128;
    const int lr = lane >> 2;
    const int lc = lane & 3;
    const int arow = tid >> 2;
    const int c16 = tid & 3;

    float acc[4][4][4];
    #pragma unroll
    for (int i = 0; i < 4; i++)
        #pragma unroll
        for (int j = 0; j < 4; j++)
            #pragma unroll
            for (int r = 0; r < 4; r++) acc[i][j][r] = 0.f;

    const int KT = K >> 5;
    auto issue = [&](int buf, int k0) {
        __half* Ad = hs + buf * HBUF;
        __half* Bd = hs + 3 * HBUF + buf * HBUF;
        #pragma unroll
        for (int i = 0; i < 2; i++) {
            int row = arow + i * 64;
            uint32_t d = (uint32_t)__cvta_generic_to_shared(Ad + row * HSTR + c16 * 8);
            CP16(d, A + (size_t)(brow + row) * K + k0 + c16 * 8);
        }
        #pragma unroll
        for (int i = 0; i < 2; i++) {
            int row = arow + i * 64;
            uint32_t d = (uint32_t)__cvta_generic_to_shared(Bd + row * HSTR + c16 * 8);
            CP16(d, Bt + (size_t)(bcol + row) * K + k0 + c16 * 8);
        }
        asm volatile("cp.async.commit_group;" ::);
    };

    issue(0, 0);
    if (KT > 1) issue(1, 32);
    for (int kt = 0; kt < KT; kt++) {
        asm volatile("cp.async.wait_group 1;" ::);
        __syncthreads();
        if (kt + 2 < KT) issue((kt + 2) % 3, (kt + 2) << 5);
        const int buf = kt % 3;
        const __half* Ad = hs + buf * HBUF;
        const __half* Bd = hs + 3 * HBUF + buf * HBUF;
        #pragma unroll
        for (int ks = 0; ks < 2; ks++) {
            const int kb = ks * 16 + 2 * lc;
            uint32_t af[4][4], bf[4][2];
            #pragma unroll
            for (int mi = 0; mi < 4; mi++) {
                int r0 = wm + mi * 16 + lr;
                af[mi][0] = *(const uint32_t*)(Ad + r0 * HSTR + kb);
                af[mi][1] = *(const uint32_t*)(Ad + (r0 + 8) * HSTR + kb);
                af[mi][2] = *(const uint32_t*)(Ad + r0 * HSTR + kb + 8);
                af[mi][3] = *(const uint32_t*)(Ad + (r0 + 8) * HSTR + kb + 8);
            }
            #pragma unroll
            for (int nj = 0; nj < 4; nj++) {
                int cc = wn + nj * 8 + lr;
                bf[nj][0] = *(const uint32_t*)(Bd + cc * HSTR + kb);
                bf[nj][1] = *(const uint32_t*)(Bd + cc * HSTR + kb + 8);
            }
            #pragma unroll
            for (int mi = 0; mi < 4; mi++)
                #pragma unroll
                for (int nj = 0; nj < 4; nj++)
                    MMA_F16(acc[mi][nj], af[mi], bf[nj]);
        }
    }
    #pragma unroll
    for (int mi = 0; mi < 4; mi++) {
        #pragma unroll
        for (int nj = 0; nj < 4; nj++) {
            int r0 = brow + wm + mi * 16 + lr;
            int c0 = bcol + wn + nj * 8 + lc * 2;
            float b0 = 0.f, b1 = 0.f;
            if (bias) { b0 = bias[c0]; b1 = bias[c0 + 1]; }
            if (OH) {
                __half* C = (__half*)Cv;
                *(__half2*)&C[(size_t)r0 * N + c0] =
                    __floats2half2_rn(acc[mi][nj][0] + b0, acc[mi][nj][1] + b1);
                *(__half2*)&C[(size_t)(r0 + 8) * N + c0] =
                    __floats2half2_rn(acc[mi][nj][2] + b0, acc[mi][nj][3] + b1);
            } else {
                float* C = (float*)Cv;
                *(float2*)&C[(size_t)r0 * N + c0] = make_float2(acc[mi][nj][0] + b0, acc[mi][nj][1] + b1);
                *(float2*)&C[(size_t)(r0 + 8) * N + c0] = make_float2(acc[mi][nj][2] + b0, acc[mi][nj][3] + b1);
            }
        }
    }
}

// ============ fp16 sr-conv GEMM, fused im2col, split-K x4, 3-stage ============
__global__ __launch_bounds__(256, 2)
void tgemm_sr_h(const __half* __restrict__ xh, const __half* __restrict__ Bt,
                float* __restrict__ Cp) {
    const int kc = blockIdx.z;
    float* C = Cp + (size_t)kc * M_SR * 256;
    extern __shared__ __half hs[];
    const int tid  = threadIdx.x;
    const int lane = tid & 31;
    const int warp = tid >> 5;
    const int wm = (warp >> 2) * 64;
    const int wn = (warp & 3) * 32;
    const int brow = blockIdx.y * 128;
    const int bcol = blockIdx.x * 128;
    const int lr = lane >> 2;
    const int lc = lane & 3;
    const int arow = tid >> 2;
    const int c16 = tid & 3;

    const __half* px[2];
    #pragma unroll
    for (int i = 0; i < 2; i++) {
        int m = brow + arow + i * 64;
        int b = m / 196, rem = m % 196;
        int oh = rem / 14, ow = rem % 14;
        px[i] = xh + ((size_t)((b * 56 + oh * 4) * 56 + ow * 4)) * 256;
    }

    float acc[4][4][4];
    #pragma unroll
    for (int i = 0; i < 4; i++)
        #pragma unroll
        for (int j = 0; j < 4; j++)
            #pragma unroll
            for (int r = 0; r < 4; r++) acc[i][j][r] = 0.f;

    const int KT = 32;
    auto issue = [&](int buf, int k0) {
        __half* Ad = hs + buf * HBUF;
        __half* Bd = hs + 3 * HBUF + buf * HBUF;
        int kk = kc * 1024 + k0 + c16 * 8;
        int kh = kk >> 10, kw = (kk >> 8) & 3, c = kk & 255;
        int off = (kh * 56 + kw) * 256 + c;
        #pragma unroll
        for (int i = 0; i < 2; i++) {
            int row = arow + i * 64;
            uint32_t d = (uint32_t)__cvta_generic_to_shared(Ad + row * HSTR + c16 * 8);
            CP16(d, px[i] + off);
        }
        #pragma unroll
        for (int i = 0; i < 2; i++) {
            int row = arow + i * 64;
            uint32_t d = (uint32_t)__cvta_generic_to_shared(Bd + row * HSTR + c16 * 8);
            CP16(d, Bt + (size_t)(bcol + row) * 4096 + kc * 1024 + k0 + c16 * 8);
        }
        asm volatile("cp.async.commit_group;" ::);
    };

    issue(0, 0);
    issue(1, 32);
    for (int kt = 0; kt < KT; kt++) {
        asm volatile("cp.async.wait_group 1;" ::);
        __syncthreads();
        if (kt + 2 < KT) issue((kt + 2) % 3, (kt + 2) << 5);
        const int buf = kt % 3;
        const __half* Ad = hs + buf * HBUF;
        const __half* Bd = hs + 3 * HBUF + buf * HBUF;
        #pragma unroll
        for (int ks = 0; ks < 2; ks++) {
            const int kb = ks * 16 + 2 * lc;
            uint32_t af[4][4], bf[4][2];
            #pragma unroll
            for (int mi = 0; mi < 4; mi++) {
                int r0 = wm + mi * 16 + lr;
                af[mi][0] = *(const uint32_t*)(Ad + r0 * HSTR + kb);
                af[mi][1] = *(const uint32_t*)(Ad + (r0 + 8) * HSTR + kb);
                af[mi][2] = *(const uint32_t*)(Ad + r0 * HSTR + kb + 8);
                af[mi][3] = *(const uint32_t*)(Ad + (r0 + 8) * HSTR + kb + 8);
            }
            #pragma unroll
            for (int nj = 0; nj < 4; nj++) {
                int cc = wn + nj * 8 + lr;
                bf[nj][0] = *(const uint32_t*)(Bd + cc * HSTR + kb);
                bf[nj][1] = *(const uint32_t*)(Bd + cc * HSTR + kb + 8);
            }
            #pragma unroll
            for (int mi = 0; mi < 4; mi++)
                #pragma unroll
                for (int nj = 0; nj < 4; nj++)
                    MMA_F16(acc[mi][nj], af[mi], bf[nj]);
        }
    }
    #pragma unroll
    for (int mi = 0; mi < 4; mi++) {
        #pragma unroll
        for (int nj = 0; nj < 4; nj++) {
            int r0 = brow + wm + mi * 16 + lr;
            int c0 = bcol + wn + nj * 8 + lc * 2;
            *(float2*)&C[(size_t)r0 * 256 + c0] = make_float2(acc[mi][nj][0], acc[mi][nj][1]);
            *(float2*)&C[(size_t)(r0 + 8) * 256 + c0] = make_float2(acc[mi][nj][2], acc[mi][nj][3]);
        }
    }
}

// ============ fp16 proj GEMM with fused concat(x1,x2)+lepe (2-stage) ============
__global__ __launch_bounds__(256, 2)
void tgemm_proj_h(const __half* __restrict__ x1h, const __half* __restrict__ x2h,
                  const __half* __restrict__ lepeh, const __half* __restrict__ Bt,
                  const float* __restrict__ bias, float* __restrict__ C) {
    const int N = 256, K = 256;
    extern __shared__ __half hs[];
    const int tid  = threadIdx.x;
    const int lane = tid & 31;
    const int warp = tid >> 5;
    const int wm = (warp >> 2) * 64;
    const int wn = (warp & 3) * 32;
    const int brow = blockIdx.y * 128;
    const int bcol = blockIdx.x * 128;
    const int lr = lane >> 2;
    const int lc = lane & 3;
    const int arow = tid >> 2;
    const int c16 = tid & 3;

    float acc[4][4][4];
    #pragma unroll
    for (int i = 0; i < 4; i++)
        #pragma unroll
        for (int j = 0; j < 4; j++)
            #pragma unroll
            for (int r = 0; r < 4; r++) acc[i][j][r] = 0.f;

    auto issueB = [&](int buf, int k0) {
        __half* Bd = hs + 2 * HBUF + buf * HBUF;
        #pragma unroll
        for (int i = 0; i < 2; i++) {
            int row = arow + i * 64;
            uint32_t d = (uint32_t)__cvta_generic_to_shared(Bd + row * HSTR + c16 * 8);
            CP16(d, Bt + (size_t)(bcol + row) * K + k0 + c16 * 8);
        }
        asm volatile("cp.async.commit_group;" ::);
    };

    uint4 ra4[2];
    auto addh = [](uint32_t ua, uint32_t ul) {
        __half2 ha = *(__half2*)&ua, hl = *(__half2*)&ul;
        float2 fa = __half22float2(ha), fl = __half22float2(hl);
        __half2 r = __floats2half2_rn(fa.x + fl.x, fa.y + fl.y);
        return *(uint32_t*)&r;
    };
    auto loadA = [&](int k0) {
        int kk = k0 + c16 * 8;
        #pragma unroll
        for (int i = 0; i < 2; i++) {
            size_t m = (size_t)(brow + arow + i * 64);
            uint4 a = (kk < 128) ? *(const uint4*)&x1h[m * 128 + kk]
                                 : *(const uint4*)&x2h[m * 128 + kk - 128];
            uint4 l = *(const uint4*)&lepeh[m * 256 + kk];
            ra4[i].x = addh(a.x, l.x);
            ra4[i].y = addh(a.y, l.y);
            ra4[i].z = addh(a.z, l.z);
            ra4[i].w = addh(a.w, l.w);
        }
    };
    auto storeA = [&](int buf) {
        __half* Ad = hs + buf * HBUF;
        #pragma unroll
        for (int i = 0; i < 2; i++)
            *(uint4*)(Ad + (arow + i * 64) * HSTR + c16 * 8) = ra4[i];
    };

    issueB(0, 0);
    loadA(0);
    int buf = 0;
    const int KT = K >> 5;
    for (int kt = 0; kt < KT; kt++) {
        storeA(buf);
        asm volatile("cp.async.wait_group 0;" ::);
        __syncthreads();
        if (kt + 1 < KT) { issueB(buf ^ 1, (kt + 1) << 5); loadA((kt + 1) << 5); }
        const __half* Ad = hs + buf * HBUF;
        const __half* Bd = hs + 2 * HBUF + buf * HBUF;
        #pragma unroll
        for (int ks = 0; ks < 2; ks++) {
            const int kb = ks * 16 + 2 * lc;
            uint32_t af[4][4], bf[4][2];
            #pragma unroll
            for (int mi = 0; mi < 4; mi++) {
                int r0 = wm + mi * 16 + lr;
                af[mi][0] = *(const uint32_t*)(Ad + r0 * HSTR + kb);
                af[mi][1] = *(const uint32_t*)(Ad + (r0 + 8) * HSTR + kb);
                af[mi][2] = *(const uint32_t*)(Ad + r0 * HSTR + kb + 8);
                af[mi][3] = *(const uint32_t*)(Ad + (r0 + 8) * HSTR + kb + 8);
            }
            #pragma unroll
            for (int nj = 0; nj < 4; nj++) {
                int cc = wn + nj * 8 + lr;
                bf[nj][0] = *(const uint32_t*)(Bd + cc * HSTR + kb);
                bf[nj][1] = *(const uint32_t*)(Bd + cc * HSTR + kb + 8);
            }
            #pragma unroll
            for (int mi = 0; mi < 4; mi++)
                #pragma unroll
                for (int nj = 0; nj < 4; nj++)
                    MMA_F16(acc[mi][nj], af[mi], bf[nj]);
        }
        buf ^= 1;
        __syncthreads();
    }
    #pragma unroll
    for (int mi = 0; mi < 4; mi++) {
        #pragma unroll
        for (int nj = 0; nj < 4; nj++) {
            int r0 = brow + wm + mi * 16 + lr;
            int c0 = bcol + wn + nj * 8 + lc * 2;
            float b0 = bias[c0], b1 = bias[c0 + 1];
            *(float2*)&C[(size_t)r0 * N + c0] = make_float2(acc[mi][nj][0] + b0, acc[mi][nj][1] + b1);
            *(float2*)&C[(size_t)(r0 + 8) * N + c0] = make_float2(acc[mi][nj][2] + b0, acc[mi][nj][3] + b1);
        }
    }
}

// ============ depthwise 3x3, register y-walk (half in/out, R8 version) ============
__global__ void dwconv3x3(const __half* __restrict__ in, const float* __restrict__ w,
                          const float* __restrict__ bias, __half* __restrict__ out) {
    int idx = blockIdx.x * 256 + threadIdx.x;
    int c = idx & 255;
    int t = idx >> 8;
    int xx = t % WW, b = t / WW;
    float wt[9];
    #pragma unroll
    for (int i = 0; i < 9; i++) wt[i] = w[i * 256 + c];
    float bz = bias[c];
    const __half* base = in + (size_t)b * NTOK * 768 + c;
    __half* ob = out + (size_t)b * NTOK * 256 + c;
    bool xl = xx > 0, xr = xx < WW - 1;

    float rA[3] = {0.f, 0.f, 0.f}, rB[3], rC[3];
    {
        const __half* rp = base;
        rB[0] = xl ? __half2float(rp[(xx - 1) * 768]) : 0.f;
        rB[1] = __half2float(rp[xx * 768]);
        rB[2] = xr ? __half2float(rp[(xx + 1) * 768]) : 0.f;
    }
    for (int y = 0; y < HH; y++) {
        if (y + 1 < HH) {
            const __half* rp = base + (size_t)(y + 1) * WW * 768;
            rC[0] = xl ? __half2float(rp[(xx - 1) * 768]) : 0.f;
            rC[1] = __half2float(rp[xx * 768]);
            rC[2] = xr ? __half2float(rp[(xx + 1) * 768]) : 0.f;
        } else { rC[0] = rC[1] = rC[2] = 0.f; }
        float acc = bz
            + wt[0] * rA[0] + wt[1] * rA[1] + wt[2] * rA[2]
            + wt[3] * rB[0] + wt[4] * rB[1] + wt[5] * rB[2]
            + wt[6] * rC[0] + wt[7] * rC[1] + wt[8] * rC[2];
        ob[(size_t)(y * WW + xx) * 256] = __float2half_rn(acc);
        rA[0] = rB[0]; rA[1] = rB[1]; rA[2] = rB[2];
        rB[0] = rC[0]; rB[1] = rC[1]; rB[2] = rC[2];
    }
}

// ============ split-K reduce + bias + LayerNorm + GELU -> half ============
__global__ void ln_gelu4(const float* __restrict__ p, const float* __restrict__ srb,
                         const float* __restrict__ g, const float* __restrict__ bb,
                         __half* __restrict__ xb) {
    int row = blockIdx.x;
    int tid = threadIdx.x;
    const size_t S = (size_t)M_SR * 256;
    size_t off = (size_t)row * 256 + tid;
    float v = p[off] + p[S + off] + p[2 * S + off] + p[3 * S + off] + srb[tid];
    __shared__ float s1[256], s2[256];
    s1[tid] = v; s2[tid] = v * v;
    __syncthreads();
    for (int o = 128; o; o >>= 1) {
        if (tid < o) { s1[tid] += s1[tid + o]; s2[tid] += s2[tid + o]; }
        __syncthreads();
    }
    float mu  = s1[0] * (1.f / CH);
    float var = s2[0] * (1.f / CH) - mu * mu;
    float tt = (v - mu) * rsqrtf(var + 1e-5f) * g[tid] + bb[tid];
    xb[off] = __float2half_rn(0.5f * tt * (1.f + erff(tt * 0.70710678118654752f)));
}

// ============ branch-1 attention, fp16 MMA, half score storage -> occ 3 ============
// halves: Qs[64][40]=2560, Ks[224][40]=8960, Vt[32][232]=7424, Sh[64][232]=14848
// total 33792 halves = 67584 B
#define A1_SMEM 67584
__global__ __launch_bounds__(256, 3)
void attn1_mma(const __half* __restrict__ packh, const __half* __restrict__ kv1h,
               __half* __restrict__ x1h) {
    extern __shared__ __half smh[];
    __half* Qs = smh;                 // [64][40]
    __half* Ks = smh + 2560;          // [224][40] rows 196..223 zero
    __half* Vt = smh + 11520;         // [32][232] cols 196..223 zero
    __half* Sh = smh + 18944;         // [64][232]
    int bh = blockIdx.y, b = bh >> 2, h = bh & 3;
    int q0 = blockIdx.x * 64;
    int tid = threadIdx.x, lane = tid & 31, warp = tid >> 5;
    int lr = lane >> 2, lc = lane & 3;

    {
        int r = tid >> 2, ch = tid & 3;
        *(uint4*)&Qs[r * 40 + ch * 8] =
            *(const uint4*)&packh[((size_t)b * NTOK + q0 + r) * 768 + 256 + h * 32 + ch * 8];
    }
    for (int e = tid; e < 224 * 4; e += 256) {
        int r = e >> 2, ch = e & 3;
        uint4 v = make_uint4(0u, 0u, 0u, 0u);
        if (r < 196)
            v = *(const uint4*)&kv1h[((size_t)b * N1 + r) * 256 + h * 32 + ch * 8];
        *(uint4*)&Ks[r * 40 + ch * 8] = v;
    }
    for (int e = tid; e < 224 * 32; e += 256) {
        int m = e >> 5, dd = e & 31;
        __half v = __float2half_rn(0.f);
        if (m < 196) v = kv1h[((size_t)b * N1 + m) * 256 + 128 + h * 32 + dd];
        Vt[dd * 232 + m] = v;
    }
    __syncthreads();

    // scores S[64,224] = Q @ K^T (stored half, scaled); warp grid 2(m:32) x 4(n:56)
    {
        int wm = (warp >> 2) * 32, wn = (warp & 3) * 56;
        float acc[2][7][4];
        #pragma unroll
        for (int i = 0; i < 2; i++)
            #pragma unroll
            for (int j = 0; j < 7; j++)
                #pragma unroll
                for (int r = 0; r < 4; r++) acc[i][j][r] = 0.f;
        #pragma unroll
        for (int ks = 0; ks < 2; ks++) {
            const int kb = ks * 16 + 2 * lc;
            uint32_t af[2][4], bf[7][2];
            #pragma unroll
            for (int mi = 0; mi < 2; mi++) {
                int r0 = wm + mi * 16 + lr;
                af[mi][0] = *(const uint32_t*)(Qs + r0 * 40 + kb);
                af[mi][1] = *(const uint32_t*)(Qs + (r0 + 8) * 40 + kb);
                af[mi][2] = *(const uint32_t*)(Qs + r0 * 40 + kb + 8);
                af[mi][3] = *(const uint32_t*)(Qs + (r0 + 8) * 40 + kb + 8);
            }
            #pragma unroll
            for (int nj = 0; nj < 7; nj++) {
                int cc = wn + nj * 8 + lr;
                bf[nj][0] = *(const uint32_t*)(Ks + cc * 40 + kb);
                bf[nj][1] = *(const uint32_t*)(Ks + cc * 40 + kb + 8);
            }
            #pragma unroll
            for (int mi = 0; mi < 2; mi++)
                #pragma unroll
                for (int nj = 0; nj < 7; nj++)
                    MMA_F16(acc[mi][nj], af[mi], bf[nj]);
        }
        #pragma unroll
        for (int mi = 0; mi < 2; mi++)
            #pragma unroll
            for (int nj = 0; nj < 7; nj++) {
                int r0 = wm + mi * 16 + lr;
                int c0 = wn + nj * 8 + lc * 2;
                *(__half2*)&Sh[r0 * 232 + c0] =
                    __floats2half2_rn(acc[mi][nj][0] * SCALE, acc[mi][nj][1] * SCALE);
                *(__half2*)&Sh[(r0 + 8) * 232 + c0] =
                    __floats2half2_rn(acc[mi][nj][2] * SCALE, acc[mi][nj][3] * SCALE);
            }
    }
    __syncthreads();

    // softmax over cols 0..195 (cols 196..223 stay exactly 0 -> P=0)
    #pragma unroll
    for (int r = 0; r < 8; r++) {
        int row = warp * 8 + r;
        float mx = -1e30f;
        for (int m = lane; m < 196; m += 32) mx = fmaxf(mx, __half2float(Sh[row * 232 + m]));
        #pragma unroll
        for (int o = 16; o; o >>= 1) mx = fmaxf(mx, __shfl_xor_sync(0xffffffffu, mx, o));
        float sum = 0.f;
        for (int m = lane; m < 196; m += 32) {
            float p = __expf(__half2float(Sh[row * 232 + m]) - mx);
            Sh[row * 232 + m] = __float2half_rn(p);
            sum += p;
        }
        #pragma unroll
        for (int o = 16; o; o >>= 1) sum += __shfl_xor_sync(0xffffffffu, sum, o);
        float inv = 1.f / sum;
        for (int m = lane; m < 196; m += 32)
            Sh[row * 232 + m] = __float2half_rn(__half2float(Sh[row * 232 + m]) * inv);
    }
    __syncthreads();

    // out = P[64,224] @ V[224,32]; warp grid 4(m:16) x 2(n:16); 14 ksteps; P loaded raw
    {
        int wm = (warp >> 1) * 16, wn = (warp & 1) * 16;
        float acc[2][4];
        #pragma unroll
        for (int j = 0; j < 2; j++)
            #pragma unroll
            for (int r = 0; r < 4; r++) acc[j][r] = 0.f;
        #pragma unroll 7
        for (int ks = 0; ks < 14; ks++) {
            const int k = ks * 16 + 2 * lc;
            uint32_t af[4], bf[2][2];
            af[0] = *(const uint32_t*)(Sh + (wm + lr) * 232 + k);
            af[1] = *(const uint32_t*)(Sh + (wm + 8 + lr) * 232 + k);
            af[2] = *(const uint32_t*)(Sh + (wm + lr) * 232 + k + 8);
            af[3] = *(const uint32_t*)(Sh + (wm + 8 + lr) * 232 + k + 8);
            #pragma unroll
            for (int nj = 0; nj < 2; nj++) {
                int cc = wn + nj * 8 + lr;
                bf[nj][0] = *(const uint32_t*)(Vt + cc * 232 + k);
                bf[nj][1] = *(const uint32_t*)(Vt + cc * 232 + k + 8);
            }
            MMA_F16(acc[0], af, bf[0]);
            MMA_F16(acc[1], af, bf[1]);
        }
        #pragma unroll
        for (int nj = 0; nj < 2; nj++) {
            int r0 = q0 + wm + lr;
            int c0 = wn + nj * 8 + lc * 2;
            *(__half2*)&x1h[((size_t)b * NTOK + r0) * 128 + h * 32 + c0] =
                __floats2half2_rn(acc[nj][0], acc[nj][1]);
            *(__half2*)&x1h[((size_t)b * NTOK + r0 + 8) * 128 + h * 32 + c0] =
                __floats2half2_rn(acc[nj][2], acc[nj][3]);
        }
    }
}

// ============ branch-2 window attention, fp16 MMA, half scores, 2 windows/CTA -> occ 4 ============
// per-window halves: Qs[64][40]=2560, Ks[64][40]=2560, Vt[32][72]=2304, Sh[64][72]=4608
// = 12032 halves = 24064 B; x2 = 48128 B
#define A2_WBYTES 24064
#define A2_SMEM (2 * A2_WBYTES)
__global__ __launch_bounds__(256, 4)
void attn2_mma(const __half* __restrict__ packh, __half* __restrict__ x2h) {
    extern __shared__ char smc[];
    int bh = blockIdx.y, b = bh >> 2, h = bh & 3;
    int tid = threadIdx.x, lane = tid & 31, warp = tid >> 5;
    int wslot = warp >> 2, w4 = warp & 3;
    int lr = lane >> 2, lc = lane & 3;
    int win = blockIdx.x * 2 + wslot;
    int wr = win >> 3, wc = win & 7;
    __half* wbase = (__half*)(smc + wslot * A2_WBYTES);
    __half* Qs = wbase;              // [64][40], rows 49..63 zero
    __half* Ks = wbase + 2560;       // [64][40], rows 49..63 zero
    __half* Vt = wbase + 5120;       // [32][72], cols 49..63 zero
    __half* Sh = wbase + 7424;       // [64][72]
    int wt = tid & 127;

    for (int e = wt; e < 64 * 4; e += 128) {
        int r = e >> 2, ch = e & 3;
        uint4 q = make_uint4(0u, 0u, 0u, 0u), k = q;
        if (r < 49) {
            int n = (wr * 7 + r / 7) * 56 + wc * 7 + r % 7;
            size_t rb = ((size_t)b * NTOK + n) * 768;
            q = *(const uint4*)&packh[rb + 384 + h * 32 + ch * 8];
            k = *(const uint4*)&packh[rb + 512 + h * 32 + ch * 8];
        }
        *(uint4*)&Qs[r * 40 + ch * 8] = q;
        *(uint4*)&Ks[r * 40 + ch * 8] = k;
    }
    for (int e = wt; e < 64 * 32; e += 128) {
        int m = e >> 5, dd = e & 31;
        __half v = __float2half_rn(0.f);
        if (m < 49) {
            int n = (wr * 7 + m / 7) * 56 + wc * 7 + m % 7;
            v = packh[((size_t)b * NTOK + n) * 768 + 640 + h * 32 + dd];
        }
        Vt[dd * 72 + m] = v;
    }
    __syncthreads();

    // scores: warp w4 rows [w4*16,+16), 8 n-tiles; store half scaled
    int wm = w4 * 16;
    {
        float acc[8][4];
        #pragma unroll
        for (int j = 0; j < 8; j++)
            #pragma unroll
            for (int r = 0; r < 4; r++) acc[j][r] = 0.f;
        #pragma unroll
        for (int ks = 0; ks < 2; ks++) {
            const int kb = ks * 16 + 2 * lc;
            uint32_t af[4], bf[8][2];
            af[0] = *(const uint32_t*)(Qs + (wm + lr) * 40 + kb);
            af[1] = *(const uint32_t*)(Qs + (wm + 8 + lr) * 40 + kb);
            af[2] = *(const uint32_t*)(Qs + (wm + lr) * 40 + kb + 8);
            af[3] = *(const uint32_t*)(Qs + (wm + 8 + lr) * 40 + kb + 8);
            #pragma unroll
            for (int nj = 0; nj < 8; nj++) {
                int cc = nj * 8 + lr;
                bf[nj][0] = *(const uint32_t*)(Ks + cc * 40 + kb);
                bf[nj][1] = *(const uint32_t*)(Ks + cc * 40 + kb + 8);
            }
            #pragma unroll
            for (int nj = 0; nj < 8; nj++)
                MMA_F16(acc[nj], af, bf[nj]);
        }
        #pragma unroll
        for (int nj = 0; nj < 8; nj++) {
            int c0 = nj * 8 + lc * 2;
            *(__half2*)&Sh[(wm + lr) * 72 + c0] =
                __floats2half2_rn(acc[nj][0] * SCALE, acc[nj][1] * SCALE);
            *(__half2*)&Sh[(wm + 8 + lr) * 72 + c0] =
                __floats2half2_rn(acc[nj][2] * SCALE, acc[nj][3] * SCALE);
        }
    }
    __syncthreads();

    // softmax rows < 49 over cols 0..48 (cols 49..63 stay exactly 0)
    for (int row = w4; row < 49; row += 4) {
        float mx = -1e30f;
        for (int m = lane; m < 49; m += 32) mx = fmaxf(mx, __half2float(Sh[row * 72 + m]));
        #pragma unroll
        for (int o = 16; o; o >>= 1) mx = fmaxf(mx, __shfl_xor_sync(0xffffffffu, mx, o));
        float sum = 0.f;
        for (int m = lane; m < 49; m += 32) {
            float p = __expf(__half2float(Sh[row * 72 + m]) - mx);
            Sh[row * 72 + m] = __float2half_rn(p);
            sum += p;
        }
        #pragma unroll
        for (int o = 16; o; o >>= 1) sum += __shfl_xor_sync(0xffffffffu, sum, o);
        float inv = 1.f / sum;
        for (int m = lane; m < 49; m += 32)
            Sh[row * 72 + m] = __float2half_rn(__half2float(Sh[row * 72 + m]) * inv);
    }
    __syncthreads();

    // out = P[64,64] @ V[64,32]; 4 ksteps; P loaded raw
    {
        float acc[4][4];
        #pragma unroll
        for (int j = 0; j < 4; j++)
            #pragma unroll
            for (int r = 0; r < 4; r++) acc[j][r] = 0.f;
        #pragma unroll
        for (int ks = 0; ks < 4; ks++) {
            const int k = ks * 16 + 2 * lc;
            uint32_t af[4], bf[4][2];
            af[0] = *(const uint32_t*)(Sh + (wm + lr) * 72 + k);
            af[1] = *(const uint32_t*)(Sh + (wm + 8 + lr) * 72 + k);
            af[2] = *(const uint32_t*)(Sh + (wm + lr) * 72 + k + 8);
            af[3] = *(const uint32_t*)(Sh + (wm + 8 + lr) * 72 + k + 8);
            #pragma unroll
            for (int nj = 0; nj < 4; nj++) {
                int cc = nj * 8 + lr;
                bf[nj][0] = *(const uint32_t*)(Vt + cc * 72 + k);
                bf[nj][1] = *(const uint32_t*)(Vt + cc * 72 + k + 8);
            }
            #pragma unroll
            for (int nj = 0; nj < 4; nj++)
                MMA_F16(acc[nj], af, bf[nj]);
        }
        int r1 = wm + lr, r2 = wm + 8 + lr;
        #pragma unroll
        for (int nj = 0; nj < 4; nj++) {
            int c0 = nj * 8 + lc * 2;
            if (r1 < 49) {
                int n = (wr * 7 + r1 / 7) * 56 + wc * 7 + r1 % 7;
                *(__half2*)&x2h[((size_t)b * NTOK + n) * 128 + h * 32 + c0] =
                    __floats2half2_rn(acc[nj][0], acc[nj][1]);
            }
            if (r2 < 49) {
                int n = (wr * 7 + r2 / 7) * 56 + wc * 7 + r2 % 7;
                *(__half2*)&x2h[((size_t)b * NTOK + n) * 128 + h * 32 + c0] =
                    __floats2half2_rn(acc[nj][2], acc[nj][3]);
            }
        }
    }
}

// ---------------- host launch (R8 two-stream schedule) ----------------
extern "C" void kernel_launch(void* const* d_in, const int* in_sizes, int n_in,
                              void* d_out, int out_size) {
    const float* x           = (const float*)d_in[0];
    const float* lepe_lin_w  = (const float*)d_in[1];
    const float* lepe_lin_b  = (const float*)d_in[2];
    const float* lepe_conv_w = (const float*)d_in[3];
    const float* lepe_conv_b = (const float*)d_in[4];
    const float* sr_w        = (const float*)d_in[5];
    const float* sr_b        = (const float*)d_in[6];
    const float* norm_g      = (const float*)d_in[7];
    const float* norm_b      = (const float*)d_in[8];
    const float* q1_w        = (const float*)d_in[9];
    const float* kv1_w       = (const float*)d_in[10];
    const float* q2_w        = (const float*)d_in[11];
    const float* kv2_w       = (const float*)d_in[12];
    const float* proj_w      = (const float*)d_in[13];
    const float* proj_b      = (const float*)d_in[14];
    float* out = (float*)d_out;

    __half *xh, *wpackT, *srwT, *kv1wT, *projwT, *packh, *lepeh, *x1s, *kv1h, *x1h, *x2h;
    float *bpack, *srp;
    cudaGetSymbolAddress((void**)&xh,     g_xh);
    cudaGetSymbolAddress((void**)&wpackT, g_wpackT);
    cudaGetSymbolAddress((void**)&bpack,  g_bpack);
    cudaGetSymbolAddress((void**)&srwT,   g_srwT);
    cudaGetSymbolAddress((void**)&kv1wT,  g_kv1wT);
    cudaGetSymbolAddress((void**)&projwT, g_projwT);
    cudaGetSymbolAddress((void**)&packh,  g_packh);
    cudaGetSymbolAddress((void**)&lepeh,  g_lepeh);
    cudaGetSymbolAddress((void**)&srp,    g_srp);
    cudaGetSymbolAddress((void**)&x1s,    g_x1s);
    cudaGetSymbolAddress((void**)&kv1h,   g_kv1h);
    cudaGetSymbolAddress((void**)&x1h,    g_x1h);
    cudaGetSymbolAddress((void**)&x2h,    g_x2h);

    cudaFuncSetAttribute(tgemm_h<true>,  cudaFuncAttributeMaxDynamicSharedMemorySize, TH_SMEM);
    cudaFuncSetAttribute(tgemm_h<false>, cudaFuncAttributeMaxDynamicSharedMemorySize, TH_SMEM);
    cudaFuncSetAttribute(tgemm_sr_h,     cudaFuncAttributeMaxDynamicSharedMemorySize, TH_SMEM);
    cudaFuncSetAttribute(tgemm_proj_h,   cudaFuncAttributeMaxDynamicSharedMemorySize, TP_SMEM);
    cudaFuncSetAttribute(attn1_mma,      cudaFuncAttributeMaxDynamicSharedMemorySize, A1_SMEM);
    cudaFuncSetAttribute(attn2_mma,      cudaFuncAttributeMaxDynamicSharedMemorySize, A2_SMEM);

    static cudaStream_t s1 = nullptr;
    static cudaEvent_t evF = nullptr, evP = nullptr, evJ = nullptr;
    if (!s1) {
        cudaStreamCreateWithFlags(&s1, cudaStreamNonBlocking);
        cudaEventCreateWithFlags(&evF, cudaEventDisableTiming);
        cudaEventCreateWithFlags(&evP, cudaEventDisableTiming);
        cudaEventCreateWithFlags(&evJ, cudaEventDisableTiming);
    }

    // main: weight pack + x conversion
    pack_weightsT<<<768, 256>>>(lepe_lin_w, lepe_lin_b, q1_w, q2_w, kv2_w, wpackT, bpack);
    cvt_x<<<(M_ALL * 256 / 4) / 256, 256>>>(x, xh);
    cudaEventRecord(evF, 0);

    // s1: sr chain
    roundT<<<4096, 256, 0, s1>>>(sr_w, kv1_w, proj_w, srwT, kv1wT, projwT);
    cudaStreamWaitEvent(s1, evF, 0);
    tgemm_sr_h<<<dim3(2, M_SR / 128, 4), 256, TH_SMEM, s1>>>(xh, srwT, srp);
    ln_gelu4<<<M_SR, 256, 0, s1>>>(srp, sr_b, norm_g, norm_b, x1s);
    tgemm_h<true><<<dim3(2, M_SR / 128), 256, TH_SMEM, s1>>>(x1s, kv1wT, nullptr, kv1h, M_SR, 256, 256);

    // main: merged projection GEMM (half out) + consumers
    tgemm_h<true><<<dim3(6, M_ALL / 128), 256, TH_SMEM>>>(xh, wpackT, bpack, packh, M_ALL, 768, 256);
    cudaEventRecord(evP, 0);
    dwconv3x3<<<(BATCH * WW * CH) / 256, 256>>>(packh, lepe_conv_w, lepe_conv_b, lepeh);
    attn2_mma<<<dim3(32, BATCH * H2), 256, A2_SMEM>>>(packh, x2h);

    // s1: attn1 after pack ready
    cudaStreamWaitEvent(s1, evP, 0);
    attn1_mma<<<dim3(NTOK / 64, BATCH * H2), 256, A1_SMEM, s1>>>(packh, kv1h, x1h);
    cudaEventRecord(evJ, s1);

    // join + final projection (fp32 out)
    cudaStreamWaitEvent(0, evJ, 0);
    tgemm_proj_h<<<dim3(2, M_ALL / 128), 256, TP_SMEM>>>(x1h, x2h, lepeh, projwT, proj_b, out);
}

// round 15
// speedup vs baseline: 1.1903x; 1.0198x over previous
#include <cuda_runtime.h>
#include <cuda_fp16.h>
#include <cstdint>

#define BATCH 32
#define HH 56
#define WW 56
#define NTOK (HH*WW)            // 3136
#define CH 256
#define H2 4
#define M_ALL (BATCH*NTOK)      // 100352
#define N1 196
#define M_SR (BATCH*N1)         // 6272
#define SCALE 0.17677669529663687f

// ---------------- scratch ----------------
__device__ __half g_xh    [(size_t)M_ALL*256];
__device__ __half g_wpackT[(size_t)768*256];
__device__ float  g_bpack [768];
__device__ __half g_srwT  [(size_t)256*4096];
__device__ __half g_kv1wT [(size_t)256*256];
__device__ __half g_projwT[(size_t)256*256];
__device__ __half g_packh [(size_t)M_ALL*768];  // [lepe_lin | q1 | q2 | kv2] (half)
__device__ __half g_lepeh [(size_t)M_ALL*CH];
__device__ float  g_srp   [(size_t)4*M_SR*CH];
__device__ __half g_x1s   [(size_t)M_SR*CH];
__device__ __half g_kv1h  [(size_t)M_SR*CH];
__device__ __half g_x1h   [(size_t)M_ALL*128];
__device__ __half g_x2h   [(size_t)M_ALL*128];

// ---------------- helpers ----------------
#define CP16(dst, src) \
    asm volatile("cp.async.cg.shared.global [%0], [%1], 16;" :: "r"(dst), "l"(src))
#define MMA_F16(c, a, b) \
    asm volatile("mma.sync.aligned.m16n8k16.row.col.f32.f16.f16.f32 " \
                 "{%0,%1,%2,%3},{%4,%5,%6,%7},{%8,%9},{%0,%1,%2,%3};" \
                 : "+f"((c)[0]), "+f"((c)[1]), "+f"((c)[2]), "+f"((c)[3]) \
                 : "r"((a)[0]), "r"((a)[1]), "r"((a)[2]), "r"((a)[3]), \
                   "r"((b)[0]), "r"((b)[1]))

// fp16 GEMM tile constants
#define HSTR 40
#define HBUF (128*HSTR)                 // 5120 halves = 10240 B
#define TH_SMEM (6*HBUF*2)              // 3-stage: 61440 B
#define TP_SMEM (4*HBUF*2)              // proj, 2-stage: 40960 B

// ============ prep kernels ============
__global__ void cvt_x(const float* __restrict__ x, __half* __restrict__ xh) {
    size_t i = (size_t)blockIdx.x * 256 + threadIdx.x;
    float4 v = ((const float4*)x)[i];
    __half2* o = (__half2*)xh;
    o[2 * i]     = __floats2half2_rn(v.x, v.y);
    o[2 * i + 1] = __floats2half2_rn(v.z, v.w);
}

__global__ void pack_weightsT(const float* __restrict__ lw, const float* __restrict__ lb,
                              const float* __restrict__ q1w, const float* __restrict__ q2w,
                              const float* __restrict__ kvw,
                              __half* __restrict__ wt, float* __restrict__ bp) {
    int idx = blockIdx.x * 256 + threadIdx.x;
    if (idx < 768) bp[idx] = (idx < 256) ? lb[idx] : 0.f;
    if (idx >= 768 * 256) return;
    int c = idx >> 8, k = idx & 255;
    float v;
    if (c < 256)      v = lw[k * 256 + c];
    else if (c < 384) v = q1w[k * 128 + (c - 256)];
    else if (c < 512) v = q2w[k * 128 + (c - 384)];
    else              v = kvw[k * 256 + (c - 512)];
    wt[idx] = __float2half_rn(v);
}

__global__ void roundT(const float* __restrict__ sw, const float* __restrict__ kw,
                       const float* __restrict__ pw,
                       __half* __restrict__ st, __half* __restrict__ kt,
                       __half* __restrict__ pt) {
    int i = blockIdx.x * 256 + threadIdx.x;
    if (i < 256 * 4096) {
        int c = i >> 12, k = i & 4095;
        st[i] = __float2half_rn(sw[k * 256 + c]);
    }
    if (i < 256 * 256) {
        int c = i >> 8, k = i & 255;
        kt[i] = __float2half_rn(kw[k * 256 + c]);
        pt[i] = __float2half_rn(pw[k * 256 + c]);
    }
}

// ============ fp16 GEMM, 3-stage pipeline: C[M,N] = A[M,K] @ Bt[N,K]^T (+bias) ============
template<bool OH>
__global__ __launch_bounds__(256, 2)
void tgemm_h(const __half* __restrict__ A, const __half* __restrict__ Bt,
             const float* __restrict__ bias, void* __restrict__ Cv,
             int M, int N, int K) {
    extern __shared__ __half hs[];
    const int tid  = threadIdx.x;
    const int lane = tid & 31;
    const int warp = tid >> 5;
    const int wm = (warp >> 2) * 64;
    const int wn = (warp & 3) * 32;
    const int brow = blockIdx.y * 128;
    const int bcol = blockIdx.x * 128;
    const int lr = lane >> 2;
    const int lc = lane & 3;
    const int arow = tid >> 2;
    const int c16 = tid & 3;

    float acc[4][4][4];
    #pragma unroll
    for (int i = 0; i < 4; i++)
        #pragma unroll
        for (int j = 0; j < 4; j++)
            #pragma unroll
            for (int r = 0; r < 4; r++) acc[i][j][r] = 0.f;

    const int KT = K >> 5;
    auto issue = [&](int buf, int k0) {
        __half* Ad = hs + buf * HBUF;
        __half* Bd = hs + 3 * HBUF + buf * HBUF;
        #pragma unroll
        for (int i = 0; i < 2; i++) {
            int row = arow + i * 64;
            uint32_t d = (uint32_t)__cvta_generic_to_shared(Ad + row * HSTR + c16 * 8);
            CP16(d, A + (size_t)(brow + row) * K + k0 + c16 * 8);
        }
        #pragma unroll
        for (int i = 0; i < 2; i++) {
            int row = arow + i * 64;
            uint32_t d = (uint32_t)__cvta_generic_to_shared(Bd + row * HSTR + c16 * 8);
            CP16(d, Bt + (size_t)(bcol + row) * K + k0 + c16 * 8);
        }
        asm volatile("cp.async.commit_group;" ::);
    };

    issue(0, 0);
    if (KT > 1) issue(1, 32);
    for (int kt = 0; kt < KT; kt++) {
        asm volatile("cp.async.wait_group 1;" ::);
        __syncthreads();
        if (kt + 2 < KT) issue((kt + 2) % 3, (kt + 2) << 5);
        const int buf = kt % 3;
        const __half* Ad = hs + buf * HBUF;
        const __half* Bd = hs + 3 * HBUF + buf * HBUF;
        #pragma unroll
        for (int ks = 0; ks < 2; ks++) {
            const int kb = ks * 16 + 2 * lc;
            uint32_t af[4][4], bf[4][2];
            #pragma unroll
            for (int mi = 0; mi < 4; mi++) {
                int r0 = wm + mi * 16 + lr;
                af[mi][0] = *(const uint32_t*)(Ad + r0 * HSTR + kb);
                af[mi][1] = *(const uint32_t*)(Ad + (r0 + 8) * HSTR + kb);
                af[mi][2] = *(const uint32_t*)(Ad + r0 * HSTR + kb + 8);
                af[mi][3] = *(const uint32_t*)(Ad + (r0 + 8) * HSTR + kb + 8);
            }
            #pragma unroll
            for (int nj = 0; nj < 4; nj++) {
                int cc = wn + nj * 8 + lr;
                bf[nj][0] = *(const uint32_t*)(Bd + cc * HSTR + kb);
                bf[nj][1] = *(const uint32_t*)(Bd + cc * HSTR + kb + 8);
            }
            #pragma unroll
            for (int mi = 0; mi < 4; mi++)
                #pragma unroll
                for (int nj = 0; nj < 4; nj++)
                    MMA_F16(acc[mi][nj], af[mi], bf[nj]);
        }
    }
    #pragma unroll
    for (int mi = 0; mi < 4; mi++) {
        #pragma unroll
        for (int nj = 0; nj < 4; nj++) {
            int r0 = brow + wm + mi * 16 + lr;
            int c0 = bcol + wn + nj * 8 + lc * 2;
            float b0 = 0.f, b1 = 0.f;
            if (bias) { b0 = bias[c0]; b1 = bias[c0 + 1]; }
            if (OH) {
                __half* C = (__half*)Cv;
                *(__half2*)&C[(size_t)r0 * N + c0] =
                    __floats2half2_rn(acc[mi][nj][0] + b0, acc[mi][nj][1] + b1);
                *(__half2*)&C[(size_t)(r0 + 8) * N + c0] =
                    __floats2half2_rn(acc[mi][nj][2] + b0, acc[mi][nj][3] + b1);
            } else {
                float* C = (float*)Cv;
                *(float2*)&C[(size_t)r0 * N + c0] = make_float2(acc[mi][nj][0] + b0, acc[mi][nj][1] + b1);
                *(float2*)&C[(size_t)(r0 + 8) * N + c0] = make_float2(acc[mi][nj][2] + b0, acc[mi][nj][3] + b1);
            }
        }
    }
}

// ============ fp16 sr-conv GEMM, fused im2col, split-K x4, 3-stage ============
__global__ __launch_bounds__(256, 2)
void tgemm_sr_h(const __half* __restrict__ xh, const __half* __restrict__ Bt,
                float* __restrict__ Cp) {
    const int kc = blockIdx.z;
    float* C = Cp + (size_t)kc * M_SR * 256;
    extern __shared__ __half hs[];
    const int tid  = threadIdx.x;
    const int lane = tid & 31;
    const int warp = tid >> 5;
    const int wm = (warp >> 2) * 64;
    const int wn = (warp & 3) * 32;
    const int brow = blockIdx.y * 128;
    const int bcol = blockIdx.x * 128;
    const int lr = lane >> 2;
    const int lc = lane & 3;
    const int arow = tid >> 2;
    const int c16 = tid & 3;

    const __half* px[2];
    #pragma unroll
    for (int i = 0; i < 2; i++) {
        int m = brow + arow + i * 64;
        int b = m / 196, rem = m % 196;
        int oh = rem / 14, ow = rem % 14;
        px[i] = xh + ((size_t)((b * 56 + oh * 4) * 56 + ow * 4)) * 256;
    }

    float acc[4][4][4];
    #pragma unroll
    for (int i = 0; i < 4; i++)
        #pragma unroll
        for (int j = 0; j < 4; j++)
            #pragma unroll
            for (int r = 0; r < 4; r++) acc[i][j][r] = 0.f;

    const int KT = 32;
    auto issue = [&](int buf, int k0) {
        __half* Ad = hs + buf * HBUF;
        __half* Bd = hs + 3 * HBUF + buf * HBUF;
        int kk = kc * 1024 + k0 + c16 * 8;
        int kh = kk >> 10, kw = (kk >> 8) & 3, c = kk & 255;
        int off = (kh * 56 + kw) * 256 + c;
        #pragma unroll
        for (int i = 0; i < 2; i++) {
            int row = arow + i * 64;
            uint32_t d = (uint32_t)__cvta_generic_to_shared(Ad + row * HSTR + c16 * 8);
            CP16(d, px[i] + off);
        }
        #pragma unroll
        for (int i = 0; i < 2; i++) {
            int row = arow + i * 64;
            uint32_t d = (uint32_t)__cvta_generic_to_shared(Bd + row * HSTR + c16 * 8);
            CP16(d, Bt + (size_t)(bcol + row) * 4096 + kc * 1024 + k0 + c16 * 8);
        }
        asm volatile("cp.async.commit_group;" ::);
    };

    issue(0, 0);
    issue(1, 32);
    for (int kt = 0; kt < KT; kt++) {
        asm volatile("cp.async.wait_group 1;" ::);
        __syncthreads();
        if (kt + 2 < KT) issue((kt + 2) % 3, (kt + 2) << 5);
        const int buf = kt % 3;
        const __half* Ad = hs + buf * HBUF;
        const __half* Bd = hs + 3 * HBUF + buf * HBUF;
        #pragma unroll
        for (int ks = 0; ks < 2; ks++) {
            const int kb = ks * 16 + 2 * lc;
            uint32_t af[4][4], bf[4][2];
            #pragma unroll
            for (int mi = 0; mi < 4; mi++) {
                int r0 = wm + mi * 16 + lr;
                af[mi][0] = *(const uint32_t*)(Ad + r0 * HSTR + kb);
                af[mi][1] = *(const uint32_t*)(Ad + (r0 + 8) * HSTR + kb);
                af[mi][2] = *(const uint32_t*)(Ad + r0 * HSTR + kb + 8);
                af[mi][3] = *(const uint32_t*)(Ad + (r0 + 8) * HSTR + kb + 8);
            }
            #pragma unroll
            for (int nj = 0; nj < 4; nj++) {
                int cc = wn + nj * 8 + lr;
                bf[nj][0] = *(const uint32_t*)(Bd + cc * HSTR + kb);
                bf[nj][1] = *(const uint32_t*)(Bd + cc * HSTR + kb + 8);
            }
            #pragma unroll
            for (int mi = 0; mi < 4; mi++)
                #pragma unroll
                for (int nj = 0; nj < 4; nj++)
                    MMA_F16(acc[mi][nj], af[mi], bf[nj]);
        }
    }
    #pragma unroll
    for (int mi = 0; mi < 4; mi++) {
        #pragma unroll
        for (int nj = 0; nj < 4; nj++) {
            int r0 = brow + wm + mi * 16 + lr;
            int c0 = bcol + wn + nj * 8 + lc * 2;
            *(float2*)&C[(size_t)r0 * 256 + c0] = make_float2(acc[mi][nj][0], acc[mi][nj][1]);
            *(float2*)&C[(size_t)(r0 + 8) * 256 + c0] = make_float2(acc[mi][nj][2], acc[mi][nj][3]);
        }
    }
}

// ============ fp16 proj GEMM with fused concat(x1,x2)+lepe (2-stage) ============
__global__ __launch_bounds__(256, 2)
void tgemm_proj_h(const __half* __restrict__ x1h, const __half* __restrict__ x2h,
                  const __half* __restrict__ lepeh, const __half* __restrict__ Bt,
                  const float* __restrict__ bias, float* __restrict__ C) {
    const int N = 256, K = 256;
    extern __shared__ __half hs[];
    const int tid  = threadIdx.x;
    const int lane = tid & 31;
    const int warp = tid >> 5;
    const int wm = (warp >> 2) * 64;
    const int wn = (warp & 3) * 32;
    const int brow = blockIdx.y * 128;
    const int bcol = blockIdx.x * 128;
    const int lr = lane >> 2;
    const int lc = lane & 3;
    const int arow = tid >> 2;
    const int c16 = tid & 3;

    float acc[4][4][4];
    #pragma unroll
    for (int i = 0; i < 4; i++)
        #pragma unroll
        for (int j = 0; j < 4; j++)
            #pragma unroll
            for (int r = 0; r < 4; r++) acc[i][j][r] = 0.f;

    auto issueB = [&](int buf, int k0) {
        __half* Bd = hs + 2 * HBUF + buf * HBUF;
        #pragma unroll
        for (int i = 0; i < 2; i++) {
            int row = arow + i * 64;
            uint32_t d = (uint32_t)__cvta_generic_to_shared(Bd + row * HSTR + c16 * 8);
            CP16(d, Bt + (size_t)(bcol + row) * K + k0 + c16 * 8);
        }
        asm volatile("cp.async.commit_group;" ::);
    };

    uint4 ra4[2];
    auto addh = [](uint32_t ua, uint32_t ul) {
        __half2 ha = *(__half2*)&ua, hl = *(__half2*)&ul;
        float2 fa = __half22float2(ha), fl = __half22float2(hl);
        __half2 r = __floats2half2_rn(fa.x + fl.x, fa.y + fl.y);
        return *(uint32_t*)&r;
    };
    auto loadA = [&](int k0) {
        int kk = k0 + c16 * 8;
        #pragma unroll
        for (int i = 0; i < 2; i++) {
            size_t m = (size_t)(brow + arow + i * 64);
            uint4 a = (kk < 128) ? *(const uint4*)&x1h[m * 128 + kk]
                                 : *(const uint4*)&x2h[m * 128 + kk - 128];
            uint4 l = *(const uint4*)&lepeh[m * 256 + kk];
            ra4[i].x = addh(a.x, l.x);
            ra4[i].y = addh(a.y, l.y);
            ra4[i].z = addh(a.z, l.z);
            ra4[i].w = addh(a.w, l.w);
        }
    };
    auto storeA = [&](int buf) {
        __half* Ad = hs + buf * HBUF;
        #pragma unroll
        for (int i = 0; i < 2; i++)
            *(uint4*)(Ad + (arow + i * 64) * HSTR + c16 * 8) = ra4[i];
    };

    issueB(0, 0);
    loadA(0);
    int buf = 0;
    const int KT = K >> 5;
    for (int kt = 0; kt < KT; kt++) {
        storeA(buf);
        asm volatile("cp.async.wait_group 0;" ::);
        __syncthreads();
        if (kt + 1 < KT) { issueB(buf ^ 1, (kt + 1) << 5); loadA((kt + 1) << 5); }
        const __half* Ad = hs + buf * HBUF;
        const __half* Bd = hs + 2 * HBUF + buf * HBUF;
        #pragma unroll
        for (int ks = 0; ks < 2; ks++) {
            const int kb = ks * 16 + 2 * lc;
            uint32_t af[4][4], bf[4][2];
            #pragma unroll
            for (int mi = 0; mi < 4; mi++) {
                int r0 = wm + mi * 16 + lr;
                af[mi][0] = *(const uint32_t*)(Ad + r0 * HSTR + kb);
                af[mi][1] = *(const uint32_t*)(Ad + (r0 + 8) * HSTR + kb);
                af[mi][2] = *(const uint32_t*)(Ad + r0 * HSTR + kb + 8);
                af[mi][3] = *(const uint32_t*)(Ad + (r0 + 8) * HSTR + kb + 8);
            }
            #pragma unroll
            for (int nj = 0; nj < 4; nj++) {
                int cc = wn + nj * 8 + lr;
                bf[nj][0] = *(const uint32_t*)(Bd + cc * HSTR + kb);
                bf[nj][1] = *(const uint32_t*)(Bd + cc * HSTR + kb + 8);
            }
            #pragma unroll
            for (int mi = 0; mi < 4; mi++)
                #pragma unroll
                for (int nj = 0; nj < 4; nj++)
                    MMA_F16(acc[mi][nj], af[mi], bf[nj]);
        }
        buf ^= 1;
        __syncthreads();
    }
    #pragma unroll
    for (int mi = 0; mi < 4; mi++) {
        #pragma unroll
        for (int nj = 0; nj < 4; nj++) {
            int r0 = brow + wm + mi * 16 + lr;
            int c0 = bcol + wn + nj * 8 + lc * 2;
            float b0 = bias[c0], b1 = bias[c0 + 1];
            *(float2*)&C[(size_t)r0 * N + c0] = make_float2(acc[mi][nj][0] + b0, acc[mi][nj][1] + b1);
            *(float2*)&C[(size_t)(r0 + 8) * N + c0] = make_float2(acc[mi][nj][2] + b0, acc[mi][nj][3] + b1);
        }
    }
}

// ============ depthwise 3x3, half2 vectorized (2 channels/thread) ============
__global__ void dwconv3x3(const __half* __restrict__ in, const float* __restrict__ w,
                          const float* __restrict__ bias, __half* __restrict__ out) {
    int idx = blockIdx.x * 256 + threadIdx.x;   // (b, xx, c2)
    int c2 = idx & 127;
    int t = idx >> 7;
    int xx = t % WW, b = t / WW;
    int c = c2 * 2;
    float2 wt[9];
    #pragma unroll
    for (int i = 0; i < 9; i++) wt[i] = *(const float2*)&w[i * 256 + c];
    float2 bz = *(const float2*)&bias[c];
    const __half2* base = (const __half2*)in + (size_t)b * NTOK * 384 + c2;  // 384 h2/token
    __half2* ob = (__half2*)out + (size_t)b * NTOK * 128 + c2;
    bool xl = xx > 0, xr = xx < WW - 1;

    float2 rA[3], rB[3], rC[3];
    #pragma unroll
    for (int i = 0; i < 3; i++) rA[i] = make_float2(0.f, 0.f);
    {
        rB[0] = xl ? __half22float2(base[(size_t)(xx - 1) * 384]) : make_float2(0.f, 0.f);
        rB[1] = __half22float2(base[(size_t)xx * 384]);
        rB[2] = xr ? __half22float2(base[(size_t)(xx + 1) * 384]) : make_float2(0.f, 0.f);
    }
    for (int y = 0; y < HH; y++) {
        if (y + 1 < HH) {
            const __half2* rp = base + (size_t)(y + 1) * WW * 384;
            rC[0] = xl ? __half22float2(rp[(size_t)(xx - 1) * 384]) : make_float2(0.f, 0.f);
            rC[1] = __half22float2(rp[(size_t)xx * 384]);
            rC[2] = xr ? __half22float2(rp[(size_t)(xx + 1) * 384]) : make_float2(0.f, 0.f);
        } else { rC[0] = rC[1] = rC[2] = make_float2(0.f, 0.f); }
        float ax = bz.x, ay = bz.y;
        #pragma unroll
        for (int i = 0; i < 3; i++) {
            ax += wt[i].x * rA[i].x + wt[3 + i].x * rB[i].x + wt[6 + i].x * rC[i].x;
            ay += wt[i].y * rA[i].y + wt[3 + i].y * rB[i].y + wt[6 + i].y * rC[i].y;
        }
        ob[(size_t)(y * WW + xx) * 128] = __floats2half2_rn(ax, ay);
        #pragma unroll
        for (int i = 0; i < 3; i++) { rA[i] = rB[i]; rB[i] = rC[i]; }
    }
}

// ============ split-K reduce + bias + LayerNorm + GELU -> half (shfl reduce) ============
__global__ void ln_gelu4(const float* __restrict__ p, const float* __restrict__ srb,
                         const float* __restrict__ g, const float* __restrict__ bb,
                         __half* __restrict__ xb) {
    int row = blockIdx.x;
    int tid = threadIdx.x, lane = tid & 31, warp = tid >> 5;
    const size_t S = (size_t)M_SR * 256;
    size_t off = (size_t)row * 256 + tid;
    float v = p[off] + p[S + off] + p[2 * S + off] + p[3 * S + off] + srb[tid];
    float s1 = v, s2 = v * v;
    #pragma unroll
    for (int o = 16; o; o >>= 1) {
        s1 += __shfl_xor_sync(0xffffffffu, s1, o);
        s2 += __shfl_xor_sync(0xffffffffu, s2, o);
    }
    __shared__ float w1[8], w2[8];
    if (lane == 0) { w1[warp] = s1; w2[warp] = s2; }
    __syncthreads();
    if (warp == 0) {
        float a = (lane < 8) ? w1[lane] : 0.f;
        float bq = (lane < 8) ? w2[lane] : 0.f;
        #pragma unroll
        for (int o = 4; o; o >>= 1) {
            a += __shfl_xor_sync(0xffffffffu, a, o);
            bq += __shfl_xor_sync(0xffffffffu, bq, o);
        }
        if (lane == 0) { w1[0] = a; w2[0] = bq; }
    }
    __syncthreads();
    float mu  = w1[0] * (1.f / CH);
    float var = w2[0] * (1.f / CH) - mu * mu;
    float tt = (v - mu) * rsqrtf(var + 1e-5f) * g[tid] + bb[tid];
    xb[off] = __float2half_rn(0.5f * tt * (1.f + erff(tt * 0.70710678118654752f)));
}

// ============ branch-1 attention, fp16 MMA, half score storage -> occ 3 ============
#define A1_SMEM 67584
__global__ __launch_bounds__(256, 3)
void attn1_mma(const __half* __restrict__ packh, const __half* __restrict__ kv1h,
               __half* __restrict__ x1h) {
    extern __shared__ __half smh[];
    __half* Qs = smh;                 // [64][40]
    __half* Ks = smh + 2560;          // [224][40] rows 196..223 zero
    __half* Vt = smh + 11520;         // [32][232] cols 196..223 zero
    __half* Sh = smh + 18944;         // [64][232]
    int bh = blockIdx.y, b = bh >> 2, h = bh & 3;
    int q0 = blockIdx.x * 64;
    int tid = threadIdx.x, lane = tid & 31, warp = tid >> 5;
    int lr = lane >> 2, lc = lane & 3;

    {
        int r = tid >> 2, ch = tid & 3;
        *(uint4*)&Qs[r * 40 + ch * 8] =
            *(const uint4*)&packh[((size_t)b * NTOK + q0 + r) * 768 + 256 + h * 32 + ch * 8];
    }
    for (int e = tid; e < 224 * 4; e += 256) {
        int r = e >> 2, ch = e & 3;
        uint4 v = make_uint4(0u, 0u, 0u, 0u);
        if (r < 196)
            v = *(const uint4*)&kv1h[((size_t)b * N1 + r) * 256 + h * 32 + ch * 8];
        *(uint4*)&Ks[r * 40 + ch * 8] = v;
    }
    for (int e = tid; e < 224 * 32; e += 256) {
        int m = e >> 5, dd = e & 31;
        __half v = __float2half_rn(0.f);
        if (m < 196) v = kv1h[((size_t)b * N1 + m) * 256 + 128 + h * 32 + dd];
        Vt[dd * 232 + m] = v;
    }
    __syncthreads();

    {
        int wm = (warp >> 2) * 32, wn = (warp & 3) * 56;
        float acc[2][7][4];
        #pragma unroll
        for (int i = 0; i < 2; i++)
            #pragma unroll
            for (int j = 0; j < 7; j++)
                #pragma unroll
                for (int r = 0; r < 4; r++) acc[i][j][r] = 0.f;
        #pragma unroll
        for (int ks = 0; ks < 2; ks++) {
            const int kb = ks * 16 + 2 * lc;
            uint32_t af[2][4], bf[7][2];
            #pragma unroll
            for (int mi = 0; mi < 2; mi++) {
                int r0 = wm + mi * 16 + lr;
                af[mi][0] = *(const uint32_t*)(Qs + r0 * 40 + kb);
                af[mi][1] = *(const uint32_t*)(Qs + (r0 + 8) * 40 + kb);
                af[mi][2] = *(const uint32_t*)(Qs + r0 * 40 + kb + 8);
                af[mi][3] = *(const uint32_t*)(Qs + (r0 + 8) * 40 + kb + 8);
            }
            #pragma unroll
            for (int nj = 0; nj < 7; nj++) {
                int cc = wn + nj * 8 + lr;
                bf[nj][0] = *(const uint32_t*)(Ks + cc * 40 + kb);
                bf[nj][1] = *(const uint32_t*)(Ks + cc * 40 + kb + 8);
            }
            #pragma unroll
            for (int mi = 0; mi < 2; mi++)
                #pragma unroll
                for (int nj = 0; nj < 7; nj++)
                    MMA_F16(acc[mi][nj], af[mi], bf[nj]);
        }
        #pragma unroll
        for (int mi = 0; mi < 2; mi++)
            #pragma unroll
            for (int nj = 0; nj < 7; nj++) {
                int r0 = wm + mi * 16 + lr;
                int c0 = wn + nj * 8 + lc * 2;
                *(__half2*)&Sh[r0 * 232 + c0] =
                    __floats2half2_rn(acc[mi][nj][0] * SCALE, acc[mi][nj][1] * SCALE);
                *(__half2*)&Sh[(r0 + 8) * 232 + c0] =
                    __floats2half2_rn(acc[mi][nj][2] * SCALE, acc[mi][nj][3] * SCALE);
            }
    }
    __syncthreads();

    #pragma unroll
    for (int r = 0; r < 8; r++) {
        int row = warp * 8 + r;
        float mx = -1e30f;
        for (int m = lane; m < 196; m += 32) mx = fmaxf(mx, __half2float(Sh[row * 232 + m]));
        #pragma unroll
        for (int o = 16; o; o >>= 1) mx = fmaxf(mx, __shfl_xor_sync(0xffffffffu, mx, o));
        float sum = 0.f;
        for (int m = lane; m < 196; m += 32) {
            float p = __expf(__half2float(Sh[row * 232 + m]) - mx);
            Sh[row * 232 + m] = __float2half_rn(p);
            sum += p;
        }
        #pragma unroll
        for (int o = 16; o; o >>= 1) sum += __shfl_xor_sync(0xffffffffu, sum, o);
        float inv = 1.f / sum;
        for (int m = lane; m < 196; m += 32)
            Sh[row * 232 + m] = __float2half_rn(__half2float(Sh[row * 232 + m]) * inv);
    }
    __syncthreads();

    {
        int wm = (warp >> 1) * 16, wn = (warp & 1) * 16;
        float acc[2][4];
        #pragma unroll
        for (int j = 0; j < 2; j++)
            #pragma unroll
            for (int r = 0; r < 4; r++) acc[j][r] = 0.f;
        #pragma unroll 7
        for (int ks = 0; ks < 14; ks++) {
            const int k = ks * 16 + 2 * lc;
            uint32_t af[4], bf[2][2];
            af[0] = *(const uint32_t*)(Sh + (wm + lr) * 232 + k);
            af[1] = *(const uint32_t*)(Sh + (wm + 8 + lr) * 232 + k);
            af[2] = *(const uint32_t*)(Sh + (wm + lr) * 232 + k + 8);
            af[3] = *(const uint32_t*)(Sh + (wm + 8 + lr) * 232 + k + 8);
            #pragma unroll
            for (int nj = 0; nj < 2; nj++) {
                int cc = wn + nj * 8 + lr;
                bf[nj][0] = *(const uint32_t*)(Vt + cc * 232 + k);
                bf[nj][1] = *(const uint32_t*)(Vt + cc * 232 + k + 8);
            }
            MMA_F16(acc[0], af, bf[0]);
            MMA_F16(acc[1], af, bf[1]);
        }
        #pragma unroll
        for (int nj = 0; nj < 2; nj++) {
            int r0 = q0 + wm + lr;
            int c0 = wn + nj * 8 + lc * 2;
            *(__half2*)&x1h[((size_t)b * NTOK + r0) * 128 + h * 32 + c0] =
                __floats2half2_rn(acc[nj][0], acc[nj][1]);
            *(__half2*)&x1h[((size_t)b * NTOK + r0 + 8) * 128 + h * 32 + c0] =
                __floats2half2_rn(acc[nj][2], acc[nj][3]);
        }
    }
}

// ============ branch-2 window attention, fp16 MMA, half scores, 2 windows/CTA -> occ 4 ============
#define A2_WBYTES 24064
#define A2_SMEM (2 * A2_WBYTES)
__global__ __launch_bounds__(256, 4)
void attn2_mma(const __half* __restrict__ packh, __half* __restrict__ x2h) {
    extern __shared__ char smc[];
    int bh = blockIdx.y, b = bh >> 2, h = bh & 3;
    int tid = threadIdx.x, lane = tid & 31, warp = tid >> 5;
    int wslot = warp >> 2, w4 = warp & 3;
    int lr = lane >> 2, lc = lane & 3;
    int win = blockIdx.x * 2 + wslot;
    int wr = win >> 3, wc = win & 7;
    __half* wbase = (__half*)(smc + wslot * A2_WBYTES);
    __half* Qs = wbase;              // [64][40], rows 49..63 zero
    __half* Ks = wbase + 2560;       // [64][40], rows 49..63 zero
    __half* Vt = wbase + 5120;       // [32][72], cols 49..63 zero
    __half* Sh = wbase + 7424;       // [64][72]
    int wt = tid & 127;

    for (int e = wt; e < 64 * 4; e += 128) {
        int r = e >> 2, ch = e & 3;
        uint4 q = make_uint4(0u, 0u, 0u, 0u), k = q;
        if (r < 49) {
            int n = (wr * 7 + r / 7) * 56 + wc * 7 + r % 7;
            size_t rb = ((size_t)b * NTOK + n) * 768;
            q = *(const uint4*)&packh[rb + 384 + h * 32 + ch * 8];
            k = *(const uint4*)&packh[rb + 512 + h * 32 + ch * 8];
        }
        *(uint4*)&Qs[r * 40 + ch * 8] = q;
        *(uint4*)&Ks[r * 40 + ch * 8] = k;
    }
    for (int e = wt; e < 64 * 32; e += 128) {
        int m = e >> 5, dd = e & 31;
        __half v = __float2half_rn(0.f);
        if (m < 49) {
            int n = (wr * 7 + m / 7) * 56 + wc * 7 + m % 7;
            v = packh[((size_t)b * NTOK + n) * 768 + 640 + h * 32 + dd];
        }
        Vt[dd * 72 + m] = v;
    }
    __syncthreads();

    int wm = w4 * 16;
    {
        float acc[8][4];
        #pragma unroll
        for (int j = 0; j < 8; j++)
            #pragma unroll
            for (int r = 0; r < 4; r++) acc[j][r] = 0.f;
        #pragma unroll
        for (int ks = 0; ks < 2; ks++) {
            const int kb = ks * 16 + 2 * lc;
            uint32_t af[4], bf[8][2];
            af[0] = *(const uint32_t*)(Qs + (wm + lr) * 40 + kb);
            af[1] = *(const uint32_t*)(Qs + (wm + 8 + lr) * 40 + kb);
            af[2] = *(const uint32_t*)(Qs + (wm + lr) * 40 + kb + 8);
            af[3] = *(const uint32_t*)(Qs + (wm + 8 + lr) * 40 + kb + 8);
            #pragma unroll
            for (int nj = 0; nj < 8; nj++) {
                int cc = nj * 8 + lr;
                bf[nj][0] = *(const uint32_t*)(Ks + cc * 40 + kb);
                bf[nj][1] = *(const uint32_t*)(Ks + cc * 40 + kb + 8);
            }
            #pragma unroll
            for (int nj = 0; nj < 8; nj++)
                MMA_F16(acc[nj], af, bf[nj]);
        }
        #pragma unroll
        for (int nj = 0; nj < 8; nj++) {
            int c0 = nj * 8 + lc * 2;
            *(__half2*)&Sh[(wm + lr) * 72 + c0] =
                __floats2half2_rn(acc[nj][0] * SCALE, acc[nj][1] * SCALE);
            *(__half2*)&Sh[(wm + 8 + lr) * 72 + c0] =
                __floats2half2_rn(acc[nj][2] * SCALE, acc[nj][3] * SCALE);
        }
    }
    __syncthreads();

    for (int row = w4; row < 49; row += 4) {
        float mx = -1e30f;
        for (int m = lane; m < 49; m += 32) mx = fmaxf(mx, __half2float(Sh[row * 72 + m]));
        #pragma unroll
        for (int o = 16; o; o >>= 1) mx = fmaxf(mx, __shfl_xor_sync(0xffffffffu, mx, o));
        float sum = 0.f;
        for (int m = lane; m < 49; m += 32) {
            float p = __expf(__half2float(Sh[row * 72 + m]) - mx);
            Sh[row * 72 + m] = __float2half_rn(p);
            sum += p;
        }
        #pragma unroll
        for (int o = 16; o; o >>= 1) sum += __shfl_xor_sync(0xffffffffu, sum, o);
        float inv = 1.f / sum;
        for (int m = lane; m < 49; m += 32)
            Sh[row * 72 + m] = __float2half_rn(__half2float(Sh[row * 72 + m]) * inv);
    }
    __syncthreads();

    {
        float acc[4][4];
        #pragma unroll
        for (int j = 0; j < 4; j++)
            #pragma unroll
            for (int r = 0; r < 4; r++) acc[j][r] = 0.f;
        #pragma unroll
        for (int ks = 0; ks < 4; ks++) {
            const int k = ks * 16 + 2 * lc;
            uint32_t af[4], bf[4][2];
            af[0] = *(const uint32_t*)(Sh + (wm + lr) * 72 + k);
            af[1] = *(const uint32_t*)(Sh + (wm + 8 + lr) * 72 + k);
            af[2] = *(const uint32_t*)(Sh + (wm + lr) * 72 + k + 8);
            af[3] = *(const uint32_t*)(Sh + (wm + 8 + lr) * 72 + k + 8);
            #pragma unroll
            for (int nj = 0; nj < 4; nj++) {
                int cc = nj * 8 + lr;
                bf[nj][0] = *(const uint32_t*)(Vt + cc * 72 + k);
                bf[nj][1] = *(const uint32_t*)(Vt + cc * 72 + k + 8);
            }
            #pragma unroll
            for (int nj = 0; nj < 4; nj++)
                MMA_F16(acc[nj], af, bf[nj]);
        }
        int r1 = wm + lr, r2 = wm + 8 + lr;
        #pragma unroll
        for (int nj = 0; nj < 4; nj++) {
            int c0 = nj * 8 + lc * 2;
            if (r1 < 49) {
                int n = (wr * 7 + r1 / 7) * 56 + wc * 7 + r1 % 7;
                *(__half2*)&x2h[((size_t)b * NTOK + n) * 128 + h * 32 + c0] =
                    __floats2half2_rn(acc[nj][0], acc[nj][1]);
            }
            if (r2 < 49) {
                int n = (wr * 7 + r2 / 7) * 56 + wc * 7 + r2 % 7;
                *(__half2*)&x2h[((size_t)b * NTOK + n) * 128 + h * 32 + c0] =
                    __floats2half2_rn(acc[nj][2], acc[nj][3]);
            }
        }
    }
}

// ---------------- host launch (R14 two-stream schedule) ----------------
extern "C" void kernel_launch(void* const* d_in, const int* in_sizes, int n_in,
                              void* d_out, int out_size) {
    const float* x           = (const float*)d_in[0];
    const float* lepe_lin_w  = (const float*)d_in[1];
    const float* lepe_lin_b  = (const float*)d_in[2];
    const float* lepe_conv_w = (const float*)d_in[3];
    const float* lepe_conv_b = (const float*)d_in[4];
    const float* sr_w        = (const float*)d_in[5];
    const float* sr_b        = (const float*)d_in[6];
    const float* norm_g      = (const float*)d_in[7];
    const float* norm_b      = (const float*)d_in[8];
    const float* q1_w        = (const float*)d_in[9];
    const float* kv1_w       = (const float*)d_in[10];
    const float* q2_w        = (const float*)d_in[11];
    const float* kv2_w       = (const float*)d_in[12];
    const float* proj_w      = (const float*)d_in[13];
    const float* proj_b      = (const float*)d_in[14];
    float* out = (float*)d_out;

    __half *xh, *wpackT, *srwT, *kv1wT, *projwT, *packh, *lepeh, *x1s, *kv1h, *x1h, *x2h;
    float *bpack, *srp;
    cudaGetSymbolAddress((void**)&xh,     g_xh);
    cudaGetSymbolAddress((void**)&wpackT, g_wpackT);
    cudaGetSymbolAddress((void**)&bpack,  g_bpack);
    cudaGetSymbolAddress((void**)&srwT,   g_srwT);
    cudaGetSymbolAddress((void**)&kv1wT,  g_kv1wT);
    cudaGetSymbolAddress((void**)&projwT, g_projwT);
    cudaGetSymbolAddress((void**)&packh,  g_packh);
    cudaGetSymbolAddress((void**)&lepeh,  g_lepeh);
    cudaGetSymbolAddress((void**)&srp,    g_srp);
    cudaGetSymbolAddress((void**)&x1s,    g_x1s);
    cudaGetSymbolAddress((void**)&kv1h,   g_kv1h);
    cudaGetSymbolAddress((void**)&x1h,    g_x1h);
    cudaGetSymbolAddress((void**)&x2h,    g_x2h);

    cudaFuncSetAttribute(tgemm_h<true>,  cudaFuncAttributeMaxDynamicSharedMemorySize, TH_SMEM);
    cudaFuncSetAttribute(tgemm_h<false>, cudaFuncAttributeMaxDynamicSharedMemorySize, TH_SMEM);
    cudaFuncSetAttribute(tgemm_sr_h,     cudaFuncAttributeMaxDynamicSharedMemorySize, TH_SMEM);
    cudaFuncSetAttribute(tgemm_proj_h,   cudaFuncAttributeMaxDynamicSharedMemorySize, TP_SMEM);
    cudaFuncSetAttribute(attn1_mma,      cudaFuncAttributeMaxDynamicSharedMemorySize, A1_SMEM);
    cudaFuncSetAttribute(attn2_mma,      cudaFuncAttributeMaxDynamicSharedMemorySize, A2_SMEM);

    static cudaStream_t s1 = nullptr;
    static cudaEvent_t evF = nullptr, evP = nullptr, evJ = nullptr;
    if (!s1) {
        cudaStreamCreateWithFlags(&s1, cudaStreamNonBlocking);
        cudaEventCreateWithFlags(&evF, cudaEventDisableTiming);
        cudaEventCreateWithFlags(&evP, cudaEventDisableTiming);
        cudaEventCreateWithFlags(&evJ, cudaEventDisableTiming);
    }

    // main: weight pack + x conversion
    pack_weightsT<<<768, 256>>>(lepe_lin_w, lepe_lin_b, q1_w, q2_w, kv2_w, wpackT, bpack);
    cvt_x<<<(M_ALL * 256 / 4) / 256, 256>>>(x, xh);
    cudaEventRecord(evF, 0);

    // s1: sr chain
    roundT<<<4096, 256, 0, s1>>>(sr_w, kv1_w, proj_w, srwT, kv1wT, projwT);
    cudaStreamWaitEvent(s1, evF, 0);
    tgemm_sr_h<<<dim3(2, M_SR / 128, 4), 256, TH_SMEM, s1>>>(xh, srwT, srp);
    ln_gelu4<<<M_SR, 256, 0, s1>>>(srp, sr_b, norm_g, norm_b, x1s);
    tgemm_h<true><<<dim3(2, M_SR / 128), 256, TH_SMEM, s1>>>(x1s, kv1wT, nullptr, kv1h, M_SR, 256, 256);

    // main: merged projection GEMM (half out) + consumers
    tgemm_h<true><<<dim3(6, M_ALL / 128), 256, TH_SMEM>>>(xh, wpackT, bpack, packh, M_ALL, 768, 256);
    cudaEventRecord(evP, 0);
    dwconv3x3<<<(BATCH * WW * 128) / 256, 256>>>(packh, lepe_conv_w, lepe_conv_b, lepeh);
    attn2_mma<<<dim3(32, BATCH * H2), 256, A2_SMEM>>>(packh, x2h);

    // s1: attn1 after pack ready
    cudaStreamWaitEvent(s1, evP, 0);
    attn1_mma<<<dim3(NTOK / 64, BATCH * H2), 256, A1_SMEM, s1>>>(packh, kv1h, x1h);
    cudaEventRecord(evJ, s1);

    // join + final projection (fp32 out)
    cudaStreamWaitEvent(0, evJ, 0);
    tgemm_proj_h<<<dim3(2, M_ALL / 128), 256, TP_SMEM>>>(x1h, x2h, lepeh, projwT, proj_b, out);
}

// round 16
// speedup vs baseline: 1.2702x; 1.0671x over previous
#include <cuda_runtime.h>
#include <cuda_fp16.h>
#include <cstdint>

#define BATCH 32
#define HH 56
#define WW 56
#define NTOK (HH*WW)            // 3136
#define CH 256
#define H2 4
#define M_ALL (BATCH*NTOK)      // 100352
#define N1 196
#define M_SR (BATCH*N1)         // 6272
#define SCALE 0.17677669529663687f

// ---------------- scratch ----------------
__device__ __half g_xh    [(size_t)M_ALL*256];
__device__ __half g_wpackT[(size_t)768*256];
__device__ float  g_bpack [768];
__device__ __half g_srwT  [(size_t)256*4096];
__device__ __half g_kv1wT [(size_t)256*256];
__device__ __half g_projwT[(size_t)256*256];
__device__ __half g_packh [(size_t)M_ALL*768];  // [lepe_lin | q1 | q2 | kv2] (half)
__device__ __half g_lepeh [(size_t)M_ALL*CH];
__device__ float  g_srp   [(size_t)4*M_SR*CH];
__device__ __half g_x1s   [(size_t)M_SR*CH];
__device__ __half g_kv1h  [(size_t)M_SR*CH];
__device__ __half g_x1h   [(size_t)M_ALL*128];
__device__ __half g_x2h   [(size_t)M_ALL*128];

// ---------------- helpers ----------------
#define CP16(dst, src) \
    asm volatile("cp.async.cg.shared.global [%0], [%1], 16;" :: "r"(dst), "l"(src))
#define MMA_F16(c, a, b) \
    asm volatile("mma.sync.aligned.m16n8k16.row.col.f32.f16.f16.f32 " \
                 "{%0,%1,%2,%3},{%4,%5,%6,%7},{%8,%9},{%0,%1,%2,%3};" \
                 : "+f"((c)[0]), "+f"((c)[1]), "+f"((c)[2]), "+f"((c)[3]) \
                 : "r"((a)[0]), "r"((a)[1]), "r"((a)[2]), "r"((a)[3]), \
                   "r"((b)[0]), "r"((b)[1]))

// fp16 GEMM tile constants
#define HSTR 40
#define HBUF (128*HSTR)                 // 5120 halves = 10240 B
#define TH_SMEM (6*HBUF*2)              // 3-stage: 61440 B
#define TP_SMEM (4*HBUF*2)              // proj, 2-stage: 40960 B

// ============ prep kernels ============
__global__ void cvt_x(const float* __restrict__ x, __half* __restrict__ xh) {
    size_t i = (size_t)blockIdx.x * 256 + threadIdx.x;
    float4 v = ((const float4*)x)[i];
    __half2* o = (__half2*)xh;
    o[2 * i]     = __floats2half2_rn(v.x, v.y);
    o[2 * i + 1] = __floats2half2_rn(v.z, v.w);
}

__global__ void pack_weightsT(const float* __restrict__ lw, const float* __restrict__ lb,
                              const float* __restrict__ q1w, const float* __restrict__ q2w,
                              const float* __restrict__ kvw,
                              __half* __restrict__ wt, float* __restrict__ bp) {
    int idx = blockIdx.x * 256 + threadIdx.x;
    if (idx < 768) bp[idx] = (idx < 256) ? lb[idx] : 0.f;
    if (idx >= 768 * 256) return;
    int c = idx >> 8, k = idx & 255;
    float v;
    if (c < 256)      v = lw[k * 256 + c];
    else if (c < 384) v = q1w[k * 128 + (c - 256)];
    else if (c < 512) v = q2w[k * 128 + (c - 384)];
    else              v = kvw[k * 256 + (c - 512)];
    wt[idx] = __float2half_rn(v);
}

__global__ void roundT(const float* __restrict__ sw, const float* __restrict__ kw,
                       const float* __restrict__ pw,
                       __half* __restrict__ st, __half* __restrict__ kt,
                       __half* __restrict__ pt) {
    int i = blockIdx.x * 256 + threadIdx.x;
    if (i < 256 * 4096) {
        int c = i >> 12, k = i & 4095;
        st[i] = __float2half_rn(sw[k * 256 + c]);
    }
    if (i < 256 * 256) {
        int c = i >> 8, k = i & 255;
        kt[i] = __float2half_rn(kw[k * 256 + c]);
        pt[i] = __float2half_rn(pw[k * 256 + c]);
    }
}

// ============ fp16 GEMM, 3-stage pipeline: C[M,N] = A[M,K] @ Bt[N,K]^T (+bias) ============
template<bool OH>
__global__ __launch_bounds__(256, 2)
void tgemm_h(const __half* __restrict__ A, const __half* __restrict__ Bt,
             const float* __restrict__ bias, void* __restrict__ Cv,
             int M, int N, int K) {
    extern __shared__ __half hs[];
    const int tid  = threadIdx.x;
    const int lane = tid & 31;
    const int warp = tid >> 5;
    const int wm = (warp >> 2) * 64;
    const int wn = (warp & 3) * 32;
    const int brow = blockIdx.y * 128;
    const int bcol = blockIdx.x * 128;
    const int lr = lane >> 2;
    const int lc = lane & 3;
    const int arow = tid >> 2;
    const int c16 = tid & 3;

    float acc[4][4][4];
    #pragma unroll
    for (int i = 0; i < 4; i++)
        #pragma unroll
        for (int j = 0; j < 4; j++)
            #pragma unroll
            for (int r = 0; r < 4; r++) acc[i][j][r] = 0.f;

    const int KT = K >> 5;
    auto issue = [&](int buf, int k0) {
        __half* Ad = hs + buf * HBUF;
        __half* Bd = hs + 3 * HBUF + buf * HBUF;
        #pragma unroll
        for (int i = 0; i < 2; i++) {
            int row = arow + i * 64;
            uint32_t d = (uint32_t)__cvta_generic_to_shared(Ad + row * HSTR + c16 * 8);
            CP16(d, A + (size_t)(brow + row) * K + k0 + c16 * 8);
        }
        #pragma unroll
        for (int i = 0; i < 2; i++) {
            int row = arow + i * 64;
            uint32_t d = (uint32_t)__cvta_generic_to_shared(Bd + row * HSTR + c16 * 8);
            CP16(d, Bt + (size_t)(bcol + row) * K + k0 + c16 * 8);
        }
        asm volatile("cp.async.commit_group;" ::);
    };

    issue(0, 0);
    if (KT > 1) issue(1, 32);
    for (int kt = 0; kt < KT; kt++) {
        asm volatile("cp.async.wait_group 1;" ::);
        __syncthreads();
        if (kt + 2 < KT) issue((kt + 2) % 3, (kt + 2) << 5);
        const int buf = kt % 3;
        const __half* Ad = hs + buf * HBUF;
        const __half* Bd = hs + 3 * HBUF + buf * HBUF;
        #pragma unroll
        for (int ks = 0; ks < 2; ks++) {
            const int kb = ks * 16 + 2 * lc;
            uint32_t af[4][4], bf[4][2];
            #pragma unroll
            for (int mi = 0; mi < 4; mi++) {
                int r0 = wm + mi * 16 + lr;
                af[mi][0] = *(const uint32_t*)(Ad + r0 * HSTR + kb);
                af[mi][1] = *(const uint32_t*)(Ad + (r0 + 8) * HSTR + kb);
                af[mi][2] = *(const uint32_t*)(Ad + r0 * HSTR + kb + 8);
                af[mi][3] = *(const uint32_t*)(Ad + (r0 + 8) * HSTR + kb + 8);
            }
            #pragma unroll
            for (int nj = 0; nj < 4; nj++) {
                int cc = wn + nj * 8 + lr;
                bf[nj][0] = *(const uint32_t*)(Bd + cc * HSTR + kb);
                bf[nj][1] = *(const uint32_t*)(Bd + cc * HSTR + kb + 8);
            }
            #pragma unroll
            for (int mi = 0; mi < 4; mi++)
                #pragma unroll
                for (int nj = 0; nj < 4; nj++)
                    MMA_F16(acc[mi][nj], af[mi], bf[nj]);
        }
    }
    #pragma unroll
    for (int mi = 0; mi < 4; mi++) {
        #pragma unroll
        for (int nj = 0; nj < 4; nj++) {
            int r0 = brow + wm + mi * 16 + lr;
            int c0 = bcol + wn + nj * 8 + lc * 2;
            float b0 = 0.f, b1 = 0.f;
            if (bias) { b0 = bias[c0]; b1 = bias[c0 + 1]; }
            if (OH) {
                __half* C = (__half*)Cv;
                *(__half2*)&C[(size_t)r0 * N + c0] =
                    __floats2half2_rn(acc[mi][nj][0] + b0, acc[mi][nj][1] + b1);
                *(__half2*)&C[(size_t)(r0 + 8) * N + c0] =
                    __floats2half2_rn(acc[mi][nj][2] + b0, acc[mi][nj][3] + b1);
            } else {
                float* C = (float*)Cv;
                *(float2*)&C[(size_t)r0 * N + c0] = make_float2(acc[mi][nj][0] + b0, acc[mi][nj][1] + b1);
                *(float2*)&C[(size_t)(r0 + 8) * N + c0] = make_float2(acc[mi][nj][2] + b0, acc[mi][nj][3] + b1);
            }
        }
    }
}

// ============ fp16 sr-conv GEMM, fused im2col, split-K x4, 3-stage ============
__global__ __launch_bounds__(256, 2)
void tgemm_sr_h(const __half* __restrict__ xh, const __half* __restrict__ Bt,
                float* __restrict__ Cp) {
    const int kc = blockIdx.z;
    float* C = Cp + (size_t)kc * M_SR * 256;
    extern __shared__ __half hs[];
    const int tid  = threadIdx.x;
    const int lane = tid & 31;
    const int warp = tid >> 5;
    const int wm = (warp >> 2) * 64;
    const int wn = (warp & 3) * 32;
    const int brow = blockIdx.y * 128;
    const int bcol = blockIdx.x * 128;
    const int lr = lane >> 2;
    const int lc = lane & 3;
    const int arow = tid >> 2;
    const int c16 = tid & 3;

    const __half* px[2];
    #pragma unroll
    for (int i = 0; i < 2; i++) {
        int m = brow + arow + i * 64;
        int b = m / 196, rem = m % 196;
        int oh = rem / 14, ow = rem % 14;
        px[i] = xh + ((size_t)((b * 56 + oh * 4) * 56 + ow * 4)) * 256;
    }

    float acc[4][4][4];
    #pragma unroll
    for (int i = 0; i < 4; i++)
        #pragma unroll
        for (int j = 0; j < 4; j++)
            #pragma unroll
            for (int r = 0; r < 4; r++) acc[i][j][r] = 0.f;

    const int KT = 32;
    auto issue = [&](int buf, int k0) {
        __half* Ad = hs + buf * HBUF;
        __half* Bd = hs + 3 * HBUF + buf * HBUF;
        int kk = kc * 1024 + k0 + c16 * 8;
        int kh = kk >> 10, kw = (kk >> 8) & 3, c = kk & 255;
        int off = (kh * 56 + kw) * 256 + c;
        #pragma unroll
        for (int i = 0; i < 2; i++) {
            int row = arow + i * 64;
            uint32_t d = (uint32_t)__cvta_generic_to_shared(Ad + row * HSTR + c16 * 8);
            CP16(d, px[i] + off);
        }
        #pragma unroll
        for (int i = 0; i < 2; i++) {
            int row = arow + i * 64;
            uint32_t d = (uint32_t)__cvta_generic_to_shared(Bd + row * HSTR + c16 * 8);
            CP16(d, Bt + (size_t)(bcol + row) * 4096 + kc * 1024 + k0 + c16 * 8);
        }
        asm volatile("cp.async.commit_group;" ::);
    };

    issue(0, 0);
    issue(1, 32);
    for (int kt = 0; kt < KT; kt++) {
        asm volatile("cp.async.wait_group 1;" ::);
        __syncthreads();
        if (kt + 2 < KT) issue((kt + 2) % 3, (kt + 2) << 5);
        const int buf = kt % 3;
        const __half* Ad = hs + buf * HBUF;
        const __half* Bd = hs + 3 * HBUF + buf * HBUF;
        #pragma unroll
        for (int ks = 0; ks < 2; ks++) {
            const int kb = ks * 16 + 2 * lc;
            uint32_t af[4][4], bf[4][2];
            #pragma unroll
            for (int mi = 0; mi < 4; mi++) {
                int r0 = wm + mi * 16 + lr;
                af[mi][0] = *(const uint32_t*)(Ad + r0 * HSTR + kb);
                af[mi][1] = *(const uint32_t*)(Ad + (r0 + 8) * HSTR + kb);
                af[mi][2] = *(const uint32_t*)(Ad + r0 * HSTR + kb + 8);
                af[mi][3] = *(const uint32_t*)(Ad + (r0 + 8) * HSTR + kb + 8);
            }
            #pragma unroll
            for (int nj = 0; nj < 4; nj++) {
                int cc = wn + nj * 8 + lr;
                bf[nj][0] = *(const uint32_t*)(Bd + cc * HSTR + kb);
                bf[nj][1] = *(const uint32_t*)(Bd + cc * HSTR + kb + 8);
            }
            #pragma unroll
            for (int mi = 0; mi < 4; mi++)
                #pragma unroll
                for (int nj = 0; nj < 4; nj++)
                    MMA_F16(acc[mi][nj], af[mi], bf[nj]);
        }
    }
    #pragma unroll
    for (int mi = 0; mi < 4; mi++) {
        #pragma unroll
        for (int nj = 0; nj < 4; nj++) {
            int r0 = brow + wm + mi * 16 + lr;
            int c0 = bcol + wn + nj * 8 + lc * 2;
            *(float2*)&C[(size_t)r0 * 256 + c0] = make_float2(acc[mi][nj][0], acc[mi][nj][1]);
            *(float2*)&C[(size_t)(r0 + 8) * 256 + c0] = make_float2(acc[mi][nj][2], acc[mi][nj][3]);
        }
    }
}

// ============ fp16 proj GEMM with fused concat(x1,x2)+lepe (2-stage) ============
__global__ __launch_bounds__(256, 2)
void tgemm_proj_h(const __half* __restrict__ x1h, const __half* __restrict__ x2h,
                  const __half* __restrict__ lepeh, const __half* __restrict__ Bt,
                  const float* __restrict__ bias, float* __restrict__ C) {
    const int N = 256, K = 256;
    extern __shared__ __half hs[];
    const int tid  = threadIdx.x;
    const int lane = tid & 31;
    const int warp = tid >> 5;
    const int wm = (warp >> 2) * 64;
    const int wn = (warp & 3) * 32;
    const int brow = blockIdx.y * 128;
    const int bcol = blockIdx.x * 128;
    const int lr = lane >> 2;
    const int lc = lane & 3;
    const int arow = tid >> 2;
    const int c16 = tid & 3;

    float acc[4][4][4];
    #pragma unroll
    for (int i = 0; i < 4; i++)
        #pragma unroll
        for (int j = 0; j < 4; j++)
            #pragma unroll
            for (int r = 0; r < 4; r++) acc[i][j][r] = 0.f;

    auto issueB = [&](int buf, int k0) {
        __half* Bd = hs + 2 * HBUF + buf * HBUF;
        #pragma unroll
        for (int i = 0; i < 2; i++) {
            int row = arow + i * 64;
            uint32_t d = (uint32_t)__cvta_generic_to_shared(Bd + row * HSTR + c16 * 8);
            CP16(d, Bt + (size_t)(bcol + row) * K + k0 + c16 * 8);
        }
        asm volatile("cp.async.commit_group;" ::);
    };

    uint4 ra4[2];
    auto addh = [](uint32_t ua, uint32_t ul) {
        __half2 ha = *(__half2*)&ua, hl = *(__half2*)&ul;
        float2 fa = __half22float2(ha), fl = __half22float2(hl);
        __half2 r = __floats2half2_rn(fa.x + fl.x, fa.y + fl.y);
        return *(uint32_t*)&r;
    };
    auto loadA = [&](int k0) {
        int kk = k0 + c16 * 8;
        #pragma unroll
        for (int i = 0; i < 2; i++) {
            size_t m = (size_t)(brow + arow + i * 64);
            uint4 a = (kk < 128) ? *(const uint4*)&x1h[m * 128 + kk]
                                 : *(const uint4*)&x2h[m * 128 + kk - 128];
            uint4 l = *(const uint4*)&lepeh[m * 256 + kk];
            ra4[i].x = addh(a.x, l.x);
            ra4[i].y = addh(a.y, l.y);
            ra4[i].z = addh(a.z, l.z);
            ra4[i].w = addh(a.w, l.w);
        }
    };
    auto storeA = [&](int buf) {
        __half* Ad = hs + buf * HBUF;
        #pragma unroll
        for (int i = 0; i < 2; i++)
            *(uint4*)(Ad + (arow + i * 64) * HSTR + c16 * 8) = ra4[i];
    };

    issueB(0, 0);
    loadA(0);
    int buf = 0;
    const int KT = K >> 5;
    for (int kt = 0; kt < KT; kt++) {
        storeA(buf);
        asm volatile("cp.async.wait_group 0;" ::);
        __syncthreads();
        if (kt + 1 < KT) { issueB(buf ^ 1, (kt + 1) << 5); loadA((kt + 1) << 5); }
        const __half* Ad = hs + buf * HBUF;
        const __half* Bd = hs + 2 * HBUF + buf * HBUF;
        #pragma unroll
        for (int ks = 0; ks < 2; ks++) {
            const int kb = ks * 16 + 2 * lc;
            uint32_t af[4][4], bf[4][2];
            #pragma unroll
            for (int mi = 0; mi < 4; mi++) {
                int r0 = wm + mi * 16 + lr;
                af[mi][0] = *(const uint32_t*)(Ad + r0 * HSTR + kb);
                af[mi][1] = *(const uint32_t*)(Ad + (r0 + 8) * HSTR + kb);
                af[mi][2] = *(const uint32_t*)(Ad + r0 * HSTR + kb + 8);
                af[mi][3] = *(const uint32_t*)(Ad + (r0 + 8) * HSTR + kb + 8);
            }
            #pragma unroll
            for (int nj = 0; nj < 4; nj++) {
                int cc = wn + nj * 8 + lr;
                bf[nj][0] = *(const uint32_t*)(Bd + cc * HSTR + kb);
                bf[nj][1] = *(const uint32_t*)(Bd + cc * HSTR + kb + 8);
            }
            #pragma unroll
            for (int mi = 0; mi < 4; mi++)
                #pragma unroll
                for (int nj = 0; nj < 4; nj++)
                    MMA_F16(acc[mi][nj], af[mi], bf[nj]);
        }
        buf ^= 1;
        __syncthreads();
    }
    #pragma unroll
    for (int mi = 0; mi < 4; mi++) {
        #pragma unroll
        for (int nj = 0; nj < 4; nj++) {
            int r0 = brow + wm + mi * 16 + lr;
            int c0 = bcol + wn + nj * 8 + lc * 2;
            float b0 = bias[c0], b1 = bias[c0 + 1];
            *(float2*)&C[(size_t)r0 * N + c0] = make_float2(acc[mi][nj][0] + b0, acc[mi][nj][1] + b1);
            *(float2*)&C[(size_t)(r0 + 8) * N + c0] = make_float2(acc[mi][nj][2] + b0, acc[mi][nj][3] + b1);
        }
    }
}

// ============ depthwise 3x3, half2 vectorized (2 channels/thread) ============
__global__ void dwconv3x3(const __half* __restrict__ in, const float* __restrict__ w,
                          const float* __restrict__ bias, __half* __restrict__ out) {
    int idx = blockIdx.x * 256 + threadIdx.x;   // (b, xx, c2)
    int c2 = idx & 127;
    int t = idx >> 7;
    int xx = t % WW, b = t / WW;
    int c = c2 * 2;
    float2 wt[9];
    #pragma unroll
    for (int i = 0; i < 9; i++) wt[i] = *(const float2*)&w[i * 256 + c];
    float2 bz = *(const float2*)&bias[c];
    const __half2* base = (const __half2*)in + (size_t)b * NTOK * 384 + c2;  // 384 h2/token
    __half2* ob = (__half2*)out + (size_t)b * NTOK * 128 + c2;
    bool xl = xx > 0, xr = xx < WW - 1;

    float2 rA[3], rB[3], rC[3];
    #pragma unroll
    for (int i = 0; i < 3; i++) rA[i] = make_float2(0.f, 0.f);
    {
        rB[0] = xl ? __half22float2(base[(size_t)(xx - 1) * 384]) : make_float2(0.f, 0.f);
        rB[1] = __half22float2(base[(size_t)xx * 384]);
        rB[2] = xr ? __half22float2(base[(size_t)(xx + 1) * 384]) : make_float2(0.f, 0.f);
    }
    for (int y = 0; y < HH; y++) {
        if (y + 1 < HH) {
            const __half2* rp = base + (size_t)(y + 1) * WW * 384;
            rC[0] = xl ? __half22float2(rp[(size_t)(xx - 1) * 384]) : make_float2(0.f, 0.f);
            rC[1] = __half22float2(rp[(size_t)xx * 384]);
            rC[2] = xr ? __half22float2(rp[(size_t)(xx + 1) * 384]) : make_float2(0.f, 0.f);
        } else { rC[0] = rC[1] = rC[2] = make_float2(0.f, 0.f); }
        float ax = bz.x, ay = bz.y;
        #pragma unroll
        for (int i = 0; i < 3; i++) {
            ax += wt[i].x * rA[i].x + wt[3 + i].x * rB[i].x + wt[6 + i].x * rC[i].x;
            ay += wt[i].y * rA[i].y + wt[3 + i].y * rB[i].y + wt[6 + i].y * rC[i].y;
        }
        ob[(size_t)(y * WW + xx) * 128] = __floats2half2_rn(ax, ay);
        #pragma unroll
        for (int i = 0; i < 3; i++) { rA[i] = rB[i]; rB[i] = rC[i]; }
    }
}

// ============ split-K reduce + bias + LayerNorm + GELU -> half (shfl reduce) ============
__global__ void ln_gelu4(const float* __restrict__ p, const float* __restrict__ srb,
                         const float* __restrict__ g, const float* __restrict__ bb,
                         __half* __restrict__ xb) {
    int row = blockIdx.x;
    int tid = threadIdx.x, lane = tid & 31, warp = tid >> 5;
    const size_t S = (size_t)M_SR * 256;
    size_t off = (size_t)row * 256 + tid;
    float v = p[off] + p[S + off] + p[2 * S + off] + p[3 * S + off] + srb[tid];
    float s1 = v, s2 = v * v;
    #pragma unroll
    for (int o = 16; o; o >>= 1) {
        s1 += __shfl_xor_sync(0xffffffffu, s1, o);
        s2 += __shfl_xor_sync(0xffffffffu, s2, o);
    }
    __shared__ float w1[8], w2[8];
    if (lane == 0) { w1[warp] = s1; w2[warp] = s2; }
    __syncthreads();
    if (warp == 0) {
        float a = (lane < 8) ? w1[lane] : 0.f;
        float bq = (lane < 8) ? w2[lane] : 0.f;
        #pragma unroll
        for (int o = 4; o; o >>= 1) {
            a += __shfl_xor_sync(0xffffffffu, a, o);
            bq += __shfl_xor_sync(0xffffffffu, bq, o);
        }
        if (lane == 0) { w1[0] = a; w2[0] = bq; }
    }
    __syncthreads();
    float mu  = w1[0] * (1.f / CH);
    float var = w2[0] * (1.f / CH) - mu * mu;
    float tt = (v - mu) * rsqrtf(var + 1e-5f) * g[tid] + bb[tid];
    xb[off] = __float2half_rn(0.5f * tt * (1.f + erff(tt * 0.70710678118654752f)));
}

// ============ branch-1 attention, fp16 MMA, half score storage -> occ 3 ============
#define A1_SMEM 67584
__global__ __launch_bounds__(256, 3)
void attn1_mma(const __half* __restrict__ packh, const __half* __restrict__ kv1h,
               __half* __restrict__ x1h) {
    extern __shared__ __half smh[];
    __half* Qs = smh;                 // [64][40]
    __half* Ks = smh + 2560;          // [224][40] rows 196..223 zero
    __half* Vt = smh + 11520;         // [32][232] cols 196..223 zero
    __half* Sh = smh + 18944;         // [64][232]
    int bh = blockIdx.y, b = bh >> 2, h = bh & 3;
    int q0 = blockIdx.x * 64;
    int tid = threadIdx.x, lane = tid & 31, warp = tid >> 5;
    int lr = lane >> 2, lc = lane & 3;

    {
        int r = tid >> 2, ch = tid & 3;
        *(uint4*)&Qs[r * 40 + ch * 8] =
            *(const uint4*)&packh[((size_t)b * NTOK + q0 + r) * 768 + 256 + h * 32 + ch * 8];
    }
    for (int e = tid; e < 224 * 4; e += 256) {
        int r = e >> 2, ch = e & 3;
        uint4 v = make_uint4(0u, 0u, 0u, 0u);
        if (r < 196)
            v = *(const uint4*)&kv1h[((size_t)b * N1 + r) * 256 + h * 32 + ch * 8];
        *(uint4*)&Ks[r * 40 + ch * 8] = v;
    }
    // V transpose: vectorized uint4 loads (8 halves of one m-row), scalar smem scatter
    for (int e = tid; e < 224 * 4; e += 256) {
        int m = e >> 2, ch = e & 3;
        uint4 v = make_uint4(0u, 0u, 0u, 0u);
        if (m < 196)
            v = *(const uint4*)&kv1h[((size_t)b * N1 + m) * 256 + 128 + h * 32 + ch * 8];
        const __half* hv = (const __half*)&v;
        #pragma unroll
        for (int j = 0; j < 8; j++)
            Vt[(ch * 8 + j) * 232 + m] = hv[j];
    }
    __syncthreads();

    {
        int wm = (warp >> 2) * 32, wn = (warp & 3) * 56;
        float acc[2][7][4];
        #pragma unroll
        for (int i = 0; i < 2; i++)
            #pragma unroll
            for (int j = 0; j < 7; j++)
                #pragma unroll
                for (int r = 0; r < 4; r++) acc[i][j][r] = 0.f;
        #pragma unroll
        for (int ks = 0; ks < 2; ks++) {
            const int kb = ks * 16 + 2 * lc;
            uint32_t af[2][4], bf[7][2];
            #pragma unroll
            for (int mi = 0; mi < 2; mi++) {
                int r0 = wm + mi * 16 + lr;
                af[mi][0] = *(const uint32_t*)(Qs + r0 * 40 + kb);
                af[mi][1] = *(const uint32_t*)(Qs + (r0 + 8) * 40 + kb);
                af[mi][2] = *(const uint32_t*)(Qs + r0 * 40 + kb + 8);
                af[mi][3] = *(const uint32_t*)(Qs + (r0 + 8) * 40 + kb + 8);
            }
            #pragma unroll
            for (int nj = 0; nj < 7; nj++) {
                int cc = wn + nj * 8 + lr;
                bf[nj][0] = *(const uint32_t*)(Ks + cc * 40 + kb);
                bf[nj][1] = *(const uint32_t*)(Ks + cc * 40 + kb + 8);
            }
            #pragma unroll
            for (int mi = 0; mi < 2; mi++)
                #pragma unroll
                for (int nj = 0; nj < 7; nj++)
                    MMA_F16(acc[mi][nj], af[mi], bf[nj]);
        }
        #pragma unroll
        for (int mi = 0; mi < 2; mi++)
            #pragma unroll
            for (int nj = 0; nj < 7; nj++) {
                int r0 = wm + mi * 16 + lr;
                int c0 = wn + nj * 8 + lc * 2;
                *(__half2*)&Sh[r0 * 232 + c0] =
                    __floats2half2_rn(acc[mi][nj][0] * SCALE, acc[mi][nj][1] * SCALE);
                *(__half2*)&Sh[(r0 + 8) * 232 + c0] =
                    __floats2half2_rn(acc[mi][nj][2] * SCALE, acc[mi][nj][3] * SCALE);
            }
    }
    __syncthreads();

    #pragma unroll
    for (int r = 0; r < 8; r++) {
        int row = warp * 8 + r;
        float mx = -1e30f;
        for (int m = lane; m < 196; m += 32) mx = fmaxf(mx, __half2float(Sh[row * 232 + m]));
        #pragma unroll
        for (int o = 16; o; o >>= 1) mx = fmaxf(mx, __shfl_xor_sync(0xffffffffu, mx, o));
        float sum = 0.f;
        for (int m = lane; m < 196; m += 32) {
            float p = __expf(__half2float(Sh[row * 232 + m]) - mx);
            Sh[row * 232 + m] = __float2half_rn(p);
            sum += p;
        }
        #pragma unroll
        for (int o = 16; o; o >>= 1) sum += __shfl_xor_sync(0xffffffffu, sum, o);
        float inv = 1.f / sum;
        for (int m = lane; m < 196; m += 32)
            Sh[row * 232 + m] = __float2half_rn(__half2float(Sh[row * 232 + m]) * inv);
    }
    __syncthreads();

    {
        int wm = (warp >> 1) * 16, wn = (warp & 1) * 16;
        float acc[2][4];
        #pragma unroll
        for (int j = 0; j < 2; j++)
            #pragma unroll
            for (int r = 0; r < 4; r++) acc[j][r] = 0.f;
        #pragma unroll 7
        for (int ks = 0; ks < 14; ks++) {
            const int k = ks * 16 + 2 * lc;
            uint32_t af[4], bf[2][2];
            af[0] = *(const uint32_t*)(Sh + (wm + lr) * 232 + k);
            af[1] = *(const uint32_t*)(Sh + (wm + 8 + lr) * 232 + k);
            af[2] = *(const uint32_t*)(Sh + (wm + lr) * 232 + k + 8);
            af[3] = *(const uint32_t*)(Sh + (wm + 8 + lr) * 232 + k + 8);
            #pragma unroll
            for (int nj = 0; nj < 2; nj++) {
                int cc = wn + nj * 8 + lr;
                bf[nj][0] = *(const uint32_t*)(Vt + cc * 232 + k);
                bf[nj][1] = *(const uint32_t*)(Vt + cc * 232 + k + 8);
            }
            MMA_F16(acc[0], af, bf[0]);
            MMA_F16(acc[1], af, bf[1]);
        }
        #pragma unroll
        for (int nj = 0; nj < 2; nj++) {
            int r0 = q0 + wm + lr;
            int c0 = wn + nj * 8 + lc * 2;
            *(__half2*)&x1h[((size_t)b * NTOK + r0) * 128 + h * 32 + c0] =
                __floats2half2_rn(acc[nj][0], acc[nj][1]);
            *(__half2*)&x1h[((size_t)b * NTOK + r0 + 8) * 128 + h * 32 + c0] =
                __floats2half2_rn(acc[nj][2], acc[nj][3]);
        }
    }
}

// ============ branch-2 window attention, fp16 MMA, half scores, 2 windows/CTA -> occ 4 ============
#define A2_WBYTES 24064
#define A2_SMEM (2 * A2_WBYTES)
__global__ __launch_bounds__(256, 4)
void attn2_mma(const __half* __restrict__ packh, __half* __restrict__ x2h) {
    extern __shared__ char smc[];
    int bh = blockIdx.y, b = bh >> 2, h = bh & 3;
    int tid = threadIdx.x, lane = tid & 31, warp = tid >> 5;
    int wslot = warp >> 2, w4 = warp & 3;
    int lr = lane >> 2, lc = lane & 3;
    int win = blockIdx.x * 2 + wslot;
    int wr = win >> 3, wc = win & 7;
    __half* wbase = (__half*)(smc + wslot * A2_WBYTES);
    __half* Qs = wbase;              // [64][40], rows 49..63 zero
    __half* Ks = wbase + 2560;       // [64][40], rows 49..63 zero
    __half* Vt = wbase + 5120;       // [32][72], cols 49..63 zero
    __half* Sh = wbase + 7424;       // [64][72]
    int wt = tid & 127;

    for (int e = wt; e < 64 * 4; e += 128) {
        int r = e >> 2, ch = e & 3;
        uint4 q = make_uint4(0u, 0u, 0u, 0u), k = q;
        if (r < 49) {
            int n = (wr * 7 + r / 7) * 56 + wc * 7 + r % 7;
            size_t rb = ((size_t)b * NTOK + n) * 768;
            q = *(const uint4*)&packh[rb + 384 + h * 32 + ch * 8];
            k = *(const uint4*)&packh[rb + 512 + h * 32 + ch * 8];
        }
        *(uint4*)&Qs[r * 40 + ch * 8] = q;
        *(uint4*)&Ks[r * 40 + ch * 8] = k;
    }
    // V transpose: vectorized loads + scalar smem scatter
    for (int e = wt; e < 64 * 4; e += 128) {
        int m = e >> 2, ch = e & 3;
        uint4 v = make_uint4(0u, 0u, 0u, 0u);
        if (m < 49) {
            int n = (wr * 7 + m / 7) * 56 + wc * 7 + m % 7;
            v = *(const uint4*)&packh[((size_t)b * NTOK + n) * 768 + 640 + h * 32 + ch * 8];
        }
        const __half* hv = (const __half*)&v;
        #pragma unroll
        for (int j = 0; j < 8; j++)
            Vt[(ch * 8 + j) * 72 + m] = hv[j];
    }
    __syncthreads();

    int wm = w4 * 16;
    {
        float acc[8][4];
        #pragma unroll
        for (int j = 0; j < 8; j++)
            #pragma unroll
            for (int r = 0; r < 4; r++) acc[j][r] = 0.f;
        #pragma unroll
        for (int ks = 0; ks < 2; ks++) {
            const int kb = ks * 16 + 2 * lc;
            uint32_t af[4], bf[8][2];
            af[0] = *(const uint32_t*)(Qs + (wm + lr) * 40 + kb);
            af[1] = *(const uint32_t*)(Qs + (wm + 8 + lr) * 40 + kb);
            af[2] = *(const uint32_t*)(Qs + (wm + lr) * 40 + kb + 8);
            af[3] = *(const uint32_t*)(Qs + (wm + 8 + lr) * 40 + kb + 8);
            #pragma unroll
            for (int nj = 0; nj < 8; nj++) {
                int cc = nj * 8 + lr;
                bf[nj][0] = *(const uint32_t*)(Ks + cc * 40 + kb);
                bf[nj][1] = *(const uint32_t*)(Ks + cc * 40 + kb + 8);
            }
            #pragma unroll
            for (int nj = 0; nj < 8; nj++)
                MMA_F16(acc[nj], af, bf[nj]);
        }
        #pragma unroll
        for (int nj = 0; nj < 8; nj++) {
            int c0 = nj * 8 + lc * 2;
            *(__half2*)&Sh[(wm + lr) * 72 + c0] =
                __floats2half2_rn(acc[nj][0] * SCALE, acc[nj][1] * SCALE);
            *(__half2*)&Sh[(wm + 8 + lr) * 72 + c0] =
                __floats2half2_rn(acc[nj][2] * SCALE, acc[nj][3] * SCALE);
        }
    }
    __syncthreads();

    for (int row = w4; row < 49; row += 4) {
        float mx = -1e30f;
        for (int m = lane; m < 49; m += 32) mx = fmaxf(mx, __half2float(Sh[row * 72 + m]));
        #pragma unroll
        for (int o = 16; o; o >>= 1) mx = fmaxf(mx, __shfl_xor_sync(0xffffffffu, mx, o));
        float sum = 0.f;
        for (int m = lane; m < 49; m += 32) {
            float p = __expf(__half2float(Sh[row * 72 + m]) - mx);
            Sh[row * 72 + m] = __float2half_rn(p);
            sum += p;
        }
        #pragma unroll
        for (int o = 16; o; o >>= 1) sum += __shfl_xor_sync(0xffffffffu, sum, o);
        float inv = 1.f / sum;
        for (int m = lane; m < 49; m += 32)
            Sh[row * 72 + m] = __float2half_rn(__half2float(Sh[row * 72 + m]) * inv);
    }
    __syncthreads();

    {
        float acc[4][4];
        #pragma unroll
        for (int j = 0; j < 4; j++)
            #pragma unroll
            for (int r = 0; r < 4; r++) acc[j][r] = 0.f;
        #pragma unroll
        for (int ks = 0; ks < 4; ks++) {
            const int k = ks * 16 + 2 * lc;
            uint32_t af[4], bf[4][2];
            af[0] = *(const uint32_t*)(Sh + (wm + lr) * 72 + k);
            af[1] = *(const uint32_t*)(Sh + (wm + 8 + lr) * 72 + k);
            af[2] = *(const uint32_t*)(Sh + (wm + lr) * 72 + k + 8);
            af[3] = *(const uint32_t*)(Sh + (wm + 8 + lr) * 72 + k + 8);
            #pragma unroll
            for (int nj = 0; nj < 4; nj++) {
                int cc = nj * 8 + lr;
                bf[nj][0] = *(const uint32_t*)(Vt + cc * 72 + k);
                bf[nj][1] = *(const uint32_t*)(Vt + cc * 72 + k + 8);
            }
            #pragma unroll
            for (int nj = 0; nj < 4; nj++)
                MMA_F16(acc[nj], af, bf[nj]);
        }
        int r1 = wm + lr, r2 = wm + 8 + lr;
        #pragma unroll
        for (int nj = 0; nj < 4; nj++) {
            int c0 = nj * 8 + lc * 2;
            if (r1 < 49) {
                int n = (wr * 7 + r1 / 7) * 56 + wc * 7 + r1 % 7;
                *(__half2*)&x2h[((size_t)b * NTOK + n) * 128 + h * 32 + c0] =
                    __floats2half2_rn(acc[nj][0], acc[nj][1]);
            }
            if (r2 < 49) {
                int n = (wr * 7 + r2 / 7) * 56 + wc * 7 + r2 % 7;
                *(__half2*)&x2h[((size_t)b * NTOK + n) * 128 + h * 32 + c0] =
                    __floats2half2_rn(acc[nj][2], acc[nj][3]);
            }
        }
    }
}

// ---------------- host launch (R14 two-stream schedule) ----------------
extern "C" void kernel_launch(void* const* d_in, const int* in_sizes, int n_in,
                              void* d_out, int out_size) {
    const float* x           = (const float*)d_in[0];
    const float* lepe_lin_w  = (const float*)d_in[1];
    const float* lepe_lin_b  = (const float*)d_in[2];
    const float* lepe_conv_w = (const float*)d_in[3];
    const float* lepe_conv_b = (const float*)d_in[4];
    const float* sr_w        = (const float*)d_in[5];
    const float* sr_b        = (const float*)d_in[6];
    const float* norm_g      = (const float*)d_in[7];
    const float* norm_b      = (const float*)d_in[8];
    const float* q1_w        = (const float*)d_in[9];
    const float* kv1_w       = (const float*)d_in[10];
    const float* q2_w        = (const float*)d_in[11];
    const float* kv2_w       = (const float*)d_in[12];
    const float* proj_w      = (const float*)d_in[13];
    const float* proj_b      = (const float*)d_in[14];
    float* out = (float*)d_out;

    __half *xh, *wpackT, *srwT, *kv1wT, *projwT, *packh, *lepeh, *x1s, *kv1h, *x1h, *x2h;
    float *bpack, *srp;
    cudaGetSymbolAddress((void**)&xh,     g_xh);
    cudaGetSymbolAddress((void**)&wpackT, g_wpackT);
    cudaGetSymbolAddress((void**)&bpack,  g_bpack);
    cudaGetSymbolAddress((void**)&srwT,   g_srwT);
    cudaGetSymbolAddress((void**)&kv1wT,  g_kv1wT);
    cudaGetSymbolAddress((void**)&projwT, g_projwT);
    cudaGetSymbolAddress((void**)&packh,  g_packh);
    cudaGetSymbolAddress((void**)&lepeh,  g_lepeh);
    cudaGetSymbolAddress((void**)&srp,    g_srp);
    cudaGetSymbolAddress((void**)&x1s,    g_x1s);
    cudaGetSymbolAddress((void**)&kv1h,   g_kv1h);
    cudaGetSymbolAddress((void**)&x1h,    g_x1h);
    cudaGetSymbolAddress((void**)&x2h,    g_x2h);

    cudaFuncSetAttribute(tgemm_h<true>,  cudaFuncAttributeMaxDynamicSharedMemorySize, TH_SMEM);
    cudaFuncSetAttribute(tgemm_h<false>, cudaFuncAttributeMaxDynamicSharedMemorySize, TH_SMEM);
    cudaFuncSetAttribute(tgemm_sr_h,     cudaFuncAttributeMaxDynamicSharedMemorySize, TH_SMEM);
    cudaFuncSetAttribute(tgemm_proj_h,   cudaFuncAttributeMaxDynamicSharedMemorySize, TP_SMEM);
    cudaFuncSetAttribute(attn1_mma,      cudaFuncAttributeMaxDynamicSharedMemorySize, A1_SMEM);
    cudaFuncSetAttribute(attn2_mma,      cudaFuncAttributeMaxDynamicSharedMemorySize, A2_SMEM);

    static cudaStream_t s1 = nullptr;
    static cudaEvent_t evF = nullptr, evP = nullptr, evJ = nullptr;
    if (!s1) {
        cudaStreamCreateWithFlags(&s1, cudaStreamNonBlocking);
        cudaEventCreateWithFlags(&evF, cudaEventDisableTiming);
        cudaEventCreateWithFlags(&evP, cudaEventDisableTiming);
        cudaEventCreateWithFlags(&evJ, cudaEventDisableTiming);
    }

    // main: weight pack + x conversion
    pack_weightsT<<<768, 256>>>(lepe_lin_w, lepe_lin_b, q1_w, q2_w, kv2_w, wpackT, bpack);
    cvt_x<<<(M_ALL * 256 / 4) / 256, 256>>>(x, xh);
    cudaEventRecord(evF, 0);

    // s1: sr chain
    roundT<<<4096, 256, 0, s1>>>(sr_w, kv1_w, proj_w, srwT, kv1wT, projwT);
    cudaStreamWaitEvent(s1, evF, 0);
    tgemm_sr_h<<<dim3(2, M_SR / 128, 4), 256, TH_SMEM, s1>>>(xh, srwT, srp);
    ln_gelu4<<<M_SR, 256, 0, s1>>>(srp, sr_b, norm_g, norm_b, x1s);
    tgemm_h<true><<<dim3(2, M_SR / 128), 256, TH_SMEM, s1>>>(x1s, kv1wT, nullptr, kv1h, M_SR, 256, 256);

    // main: merged projection GEMM (half out) + consumers
    tgemm_h<true><<<dim3(6, M_ALL / 128), 256, TH_SMEM>>>(xh, wpackT, bpack, packh, M_ALL, 768, 256);
    cudaEventRecord(evP, 0);
    dwconv3x3<<<(BATCH * WW * 128) / 256, 256>>>(packh, lepe_conv_w, lepe_conv_b, lepeh);
    attn2_mma<<<dim3(32, BATCH * H2), 256, A2_SMEM>>>(packh, x2h);

    // s1: attn1 after pack ready
    cudaStreamWaitEvent(s1, evP, 0);
    attn1_mma<<<dim3(NTOK / 64, BATCH * H2), 256, A1_SMEM, s1>>>(packh, kv1h, x1h);
    cudaEventRecord(evJ, s1);

    // join + final projection (fp32 out)
    cudaStreamWaitEvent(0, evJ, 0);
    tgemm_proj_h<<<dim3(2, M_ALL / 128), 256, TP_SMEM>>>(x1h, x2h, lepeh, projwT, proj_b, out);
}